// round 12
// baseline (speedup 1.0000x reference)
#include <cuda_runtime.h>
#include <cuda_fp16.h>
#include <cstdint>

#define CIN 256
#define COUT 256
#define NB 32
#define ZSZ (NB * COUT * 36)
#define OSZ (NB * COUT * 625)

// Winograd tile counts: x: 15x15*32 = 7200 (pad 7296 = 228*32), z: 288 (pad 384)
#define NTX 7296
#define NTZ 384
#define VSX ((size_t)NTX * 512)
#define VSZ ((size_t)NTZ * 512)

__device__ __align__(16) __half g_wU[4][16 * 256 * 256]; // [path][(pos*256+oc)*256 + cin]
__device__ float g_bias[4][COUT];
__device__ __align__(16) __half g_V[16 * NTX * 512];     // [pos][tile][comp*256+cin]
__device__ __align__(16) __half g_Vz[16 * NTZ * 512];
__device__ float g_M[2][(size_t)NTX * 16 * 256];         // [branch][tile][pos][oc]
__device__ float g_Mz[2][(size_t)NTZ * 16 * 256];
__device__ float g_zf[2][ZSZ];

struct PrepArgs {
    const float* w[4];
    const float* g[4];
    const float* b[4];
    const float* m[4];
    const float* v[4];
};

// ============================ helpers ========================================
__device__ __forceinline__ uint32_t smem_u32(const void* p) {
    uint32_t a;
    asm("{ .reg .u64 t; cvta.to.shared.u64 t, %1; cvt.u32.u64 %0, t; }"
        : "=r"(a) : "l"(p));
    return a;
}
__device__ __forceinline__ void cp16(uint32_t dst, const void* src) {
    asm volatile("cp.async.cg.shared.global [%0], [%1], 16;" :: "r"(dst), "l"(src));
}
__device__ __forceinline__ void cp_commit() {
    asm volatile("cp.async.commit_group;" ::: "memory");
}
template <int N>
__device__ __forceinline__ void cp_wait() {
    asm volatile("cp.async.wait_group %0;" :: "n"(N) : "memory");
}

#define LDSM4(r, addr)                                                         \
    asm volatile("ldmatrix.sync.aligned.m8n8.x4.shared.b16 {%0,%1,%2,%3},[%4];"\
        : "=r"((r)[0]), "=r"((r)[1]), "=r"((r)[2]), "=r"((r)[3]) : "r"(addr))

#define MMA(d, a, b0, b1)                                                      \
    asm volatile("mma.sync.aligned.m16n8k16.row.col.f32.f16.f16.f32 "          \
        "{%0,%1,%2,%3}, {%4,%5,%6,%7}, {%8,%9}, {%0,%1,%2,%3};"                \
        : "+f"((d)[0]), "+f"((d)[1]), "+f"((d)[2]), "+f"((d)[3])               \
        : "r"((a)[0]), "r"((a)[1]), "r"((a)[2]), "r"((a)[3]),                  \
          "r"(b0), "r"(b1))

__device__ __forceinline__ void hsplit(float v, __half& hi, __half& lo) {
    hi = __float2half_rn(v);
    lo = __float2half_rn(v - __half2float(hi));
}

// ============================ prep: weight transform =========================
__global__ void prep_kernel(PrepArgs a) {
    int i = blockIdx.x * blockDim.x + threadIdx.x;       // 262144 items
    int path = i >> 16;
    int oc   = (i >> 8) & 255;
    int cin  = i & 255;
    float inv = a.g[path][oc] * rsqrtf(a.v[path][oc] + 1e-5f);
    const float* wp = a.w[path] + oc * 2304 + cin * 9;
    float w[3][3];
#pragma unroll
    for (int r = 0; r < 3; r++)
#pragma unroll
        for (int c = 0; c < 3; c++) w[r][c] = wp[r * 3 + c] * inv;

    float T[4][3];
#pragma unroll
    for (int j = 0; j < 3; j++) {
        T[0][j] = w[0][j];
        T[1][j] = 0.5f * (w[0][j] + w[1][j] + w[2][j]);
        T[2][j] = 0.5f * (w[0][j] - w[1][j] + w[2][j]);
        T[3][j] = w[2][j];
    }
#pragma unroll
    for (int r = 0; r < 4; r++) {
        float U[4];
        U[0] = T[r][0];
        U[1] = 0.5f * (T[r][0] + T[r][1] + T[r][2]);
        U[2] = 0.5f * (T[r][0] - T[r][1] + T[r][2]);
        U[3] = T[r][2];
#pragma unroll
        for (int c = 0; c < 4; c++)
            g_wU[path][((size_t)((r * 4 + c) * 256 + oc)) * 256 + cin] =
                __float2half_rn(U[c]);
    }
    if (i < 1024) {
        int p2 = i >> 8, oc2 = i & 255;
        float inv2 = a.g[p2][oc2] * rsqrtf(a.v[p2][oc2] + 1e-5f);
        g_bias[p2][oc2] = a.b[p2][oc2] - a.m[p2][oc2] * inv2;
    }
}

// ============================ input transforms ===============================
__device__ __forceinline__ void wino_fwd(const float d[4][4], float V[4][4]) {
    float t[4][4];
#pragma unroll
    for (int j = 0; j < 4; j++) {
        t[0][j] = d[0][j] - d[2][j];
        t[1][j] = d[1][j] + d[2][j];
        t[2][j] = d[2][j] - d[1][j];
        t[3][j] = d[1][j] - d[3][j];
    }
#pragma unroll
    for (int i = 0; i < 4; i++) {
        V[i][0] = t[i][0] - t[i][2];
        V[i][1] = t[i][1] + t[i][2];
        V[i][2] = t[i][2] - t[i][1];
        V[i][3] = t[i][1] - t[i][3];
    }
}

#define SDSTR 129
#define XF_SD_BYTES (64 * SDSTR * 4)                 // 33024
#define XF_SV_OFF   XF_SD_BYTES
#define XF_SMEM (XF_SD_BYTES + 15 * 16 * 2 * 64 * 2) // 94464

__global__ __launch_bounds__(256)
void xform_x(const float* __restrict__ x) {
    extern __shared__ __align__(16) char xsm[];
    float* sd = (float*)xsm;
    __half* sV = (__half*)(xsm + XF_SV_OFF);         // [tile][pos][comp][64]
    const int img = blockIdx.x, cg = blockIdx.y, ty = blockIdx.z;
    const int tid = threadIdx.x;
    const int c0 = cg * 64;
    const float* src = x + ((size_t)img * 256 + c0) * 1024 + 2 * ty * 32;

#pragma unroll
    for (int k = 0; k < 32; k++) {
        int id = k * 256 + tid;
        int c = id >> 7, rc = id & 127;
        sd[c * SDSTR + rc] = src[(size_t)c * 1024 + rc];
    }
    __syncthreads();

#pragma unroll
    for (int k = 0; k < 4; k++) {
        int id = k * 256 + tid;
        if (id < 960) {
            int tx = id >> 6, c = id & 63;
            const float* p = sd + c * SDSTR + 2 * tx;
            float d[4][4], V[4][4];
#pragma unroll
            for (int i = 0; i < 4; i++)
#pragma unroll
                for (int j = 0; j < 4; j++) d[i][j] = p[i * 32 + j];
            wino_fwd(d, V);
#pragma unroll
            for (int i = 0; i < 4; i++)
#pragma unroll
                for (int j = 0; j < 4; j++) {
                    __half hi, lo;
                    hsplit(V[i][j], hi, lo);
                    int pb = (tx * 16 + (i * 4 + j)) * 128;
                    sV[pb + c]      = hi;
                    sV[pb + 64 + c] = lo;
                }
        }
    }
    __syncthreads();

#pragma unroll
    for (int k = 0; k < 15; k++) {                   // exactly 3840 uint4
        int id = k * 256 + tid;
        int q    = id & 7;
        int comp = (id >> 3) & 1;
        int pos  = (id >> 4) & 15;
        int tile = id >> 8;
        uint4 v = *(const uint4*)(sV + ((tile * 16 + pos) * 2 + comp) * 64 + q * 8);
        *(uint4*)(g_V + (size_t)pos * VSX +
                  ((size_t)img * 225 + ty * 15 + tile) * 512 +
                  comp * 256 + c0 + q * 8) = v;
    }
}

__global__ __launch_bounds__(128)
void xform_z(const float* __restrict__ z) {
    __shared__ float sd[8][64];
    __shared__ __align__(16) __half sVz[9][16][2][8];
    const int img = blockIdx.x, cg = blockIdx.y, tid = threadIdx.x;
    const float* src = z + ((size_t)img * 256 + cg * 8) * 64;
#pragma unroll
    for (int k = 0; k < 4; k++) {
        int lin = k * 128 + tid;
        sd[lin >> 6][lin & 63] = src[lin];
    }
    __syncthreads();
    if (tid < 72) {
        int tl = tid >> 3, c = tid & 7;
        int ty = tl / 3, tx = tl - ty * 3;
        float d[4][4], V[4][4];
#pragma unroll
        for (int i = 0; i < 4; i++)
#pragma unroll
            for (int j = 0; j < 4; j++)
                d[i][j] = sd[c][(2 * ty + i) * 8 + 2 * tx + j];
        wino_fwd(d, V);
#pragma unroll
        for (int i = 0; i < 4; i++)
#pragma unroll
            for (int j = 0; j < 4; j++) {
                __half hi, lo;
                hsplit(V[i][j], hi, lo);
                sVz[tl][i * 4 + j][0][c] = hi;
                sVz[tl][i * 4 + j][1][c] = lo;
            }
    }
    __syncthreads();
#pragma unroll
    for (int k = 0; k < 3; k++) {
        int cid = k * 128 + tid;
        if (cid < 288) {
            int tl = cid >> 5, pos = (cid >> 1) & 15, comp = cid & 1;
            uint4 val = *(const uint4*)&sVz[tl][pos][comp][0];
            *(uint4*)(g_Vz + (size_t)pos * VSZ +
                      ((size_t)img * 9 + tl) * 512 + comp * 256 + cg * 8) = val;
        }
    }
}

// ============================ batched GEMM ===================================
// D[128 tile, 128 oc] = V[128,256] * U[128,256]^T, 2-term fp16 A split.
// 256 threads, 8 warps (2 M x 4 N), warp tile 64x32 -> 16 warps/SM at 2 CTAs.
#define ASTR 144u
#define ABUF (128u * ASTR)        // 18432
#define BSTR 80u
#define BBUF (128u * BSTR)        // 10240
#define BOFF (2u * ABUF)          // 36864
#define GEMM_SMEM (BOFF + 2u * BBUF)   // 57344

__global__ __launch_bounds__(256, 2)
void wino_gemm() {
    extern __shared__ __align__(16) char smem[];
    const int tid = threadIdx.x, lid = tid & 31, wid = tid >> 5;
    const int warp_m = wid & 1, warp_n = wid >> 1;
    const uint32_t sBu = smem_u32(smem);

    const int bid = blockIdx.x;
    const __half *vsrc, *wsrc;
    float* mdst;
    if (bid < 3648) {
        int o = bid & 1;
        int pair = bid >> 1;
        int mt = pair % 57;
        int rest = pair / 57;
        int p = rest & 15, b = rest >> 4;
        vsrc = g_V + (size_t)p * VSX + (size_t)mt * 128 * 512;
        wsrc = g_wU[1 + 2 * b] + ((size_t)(p * 256) + o * 128) * 256;
        mdst = g_M[b] + ((size_t)mt * 128) * 4096 + p * 256 + o * 128;
    } else {
        int zb = bid - 3648;
        int q = zb / 3, mt = zb - q * 3;
        int p = q & 15; q >>= 4;
        int o = q & 1, b = q >> 1;
        vsrc = g_Vz + (size_t)p * VSZ + (size_t)mt * 128 * 512;
        wsrc = g_wU[2 * b] + ((size_t)(p * 256) + o * 128) * 256;
        mdst = g_Mz[b] + ((size_t)mt * 128) * 4096 + p * 256 + o * 128;
    }

    float acc[4][4][4];
#pragma unroll
    for (int t = 0; t < 4; t++)
#pragma unroll
        for (int j = 0; j < 4; j++)
#pragma unroll
            for (int e = 0; e < 4; e++) acc[t][j][e] = 0.f;

    auto copyAB = [&](int g) {
        const int buf = g & 1, c0 = g * 32;
#pragma unroll
        for (int k = 0; k < 4; k++) {                // A: 1024 cp16 (hi+lo)
            int id = tid + k * 256;
            int row = id >> 3, part = id & 7, comp = part >> 2, kq = part & 3;
            cp16(sBu + buf * ABUF + row * ASTR + comp * 64 + kq * 16,
                 vsrc + (size_t)row * 512 + comp * 256 + c0 + kq * 8);
        }
#pragma unroll
        for (int k = 0; k < 2; k++) {                // B: 512 cp16
            int id = tid + k * 256;
            int row = id >> 2, part = id & 3;
            cp16(sBu + BOFF + buf * BBUF + row * BSTR + part * 16,
                 wsrc + (size_t)row * 256 + c0 + part * 8);
        }
        cp_commit();
    };

    copyAB(0);
#pragma unroll 1
    for (int g = 0; g < 8; g++) {
        const int buf = g & 1;
        cp_wait<0>();
        __syncthreads();
        if (g + 1 < 8) copyAB(g + 1);   // overlaps with compute below

        uint32_t aaddr[4], baddr[2];
#pragma unroll
        for (int t = 0; t < 4; t++) {
            int m = warp_m * 64 + t * 16 + (lid & 7) + ((lid >> 3) & 1) * 8;
            aaddr[t] = sBu + buf * ABUF + m * ASTR + ((lid >> 4) << 4);
        }
#pragma unroll
        for (int j = 0; j < 2; j++) {
            int n = warp_n * 32 + j * 16 + (lid & 7) + (lid >> 4) * 8;
            baddr[j] = sBu + BOFF + buf * BBUF + n * BSTR + (((lid >> 3) & 1) << 4);
        }

#pragma unroll
        for (int ks = 0; ks < 2; ks++) {
            uint32_t ah[4][4], al[4][4], bq[2][4];
#pragma unroll
            for (int t = 0; t < 4; t++) LDSM4(ah[t], aaddr[t] + ks * 32);
#pragma unroll
            for (int t = 0; t < 4; t++) LDSM4(al[t], aaddr[t] + ks * 32 + 64);
#pragma unroll
            for (int j = 0; j < 2; j++) LDSM4(bq[j], baddr[j] + ks * 32);
            // hi*B
#pragma unroll
            for (int t = 0; t < 4; t++)
#pragma unroll
                for (int j = 0; j < 2; j++) {
                    MMA(acc[t][2 * j],     ah[t], bq[j][0], bq[j][1]);
                    MMA(acc[t][2 * j + 1], ah[t], bq[j][2], bq[j][3]);
                }
            // lo*B
#pragma unroll
            for (int t = 0; t < 4; t++)
#pragma unroll
                for (int j = 0; j < 2; j++) {
                    MMA(acc[t][2 * j],     al[t], bq[j][0], bq[j][1]);
                    MMA(acc[t][2 * j + 1], al[t], bq[j][2], bq[j][3]);
                }
        }
    }

    // epilogue: [tile][pos][oc] stores; tile stride 4096 floats
#pragma unroll
    for (int t = 0; t < 4; t++) {
        int r = warp_m * 64 + t * 16 + (lid >> 2);
#pragma unroll
        for (int jj = 0; jj < 4; jj++) {
            int c = warp_n * 32 + (jj >> 1) * 16 + (jj & 1) * 8 + (lid & 3) * 2;
            float* base = mdst + (size_t)r * 4096 + c;
            *(float2*)base = make_float2(acc[t][jj][0], acc[t][jj][1]);
            *(float2*)(base + (size_t)8 * 4096) = make_float2(acc[t][jj][2], acc[t][jj][3]);
        }
    }
}

// ============================ inverse transform: z ===========================
__global__ __launch_bounds__(256)
void inv_z() {
    __shared__ float sOut[256 * 36];
    const int img = blockIdx.x, b = blockIdx.y;
    const int oc = threadIdx.x;
    const float bs = g_bias[2 * b][oc];
    const float* Mb = g_Mz[b];
#pragma unroll
    for (int t = 0; t < 9; t++) {
        int ty = t / 3, tx = t - ty * 3;
        const float* mp = Mb + ((size_t)img * 9 + t) * 4096 + oc;
        float Mv[16];
#pragma unroll
        for (int pos = 0; pos < 16; pos++) Mv[pos] = mp[pos * 256];
        float t0[4], t1[4];
#pragma unroll
        for (int j = 0; j < 4; j++) {
            t0[j] = Mv[j] + Mv[4 + j] + Mv[8 + j];
            t1[j] = Mv[4 + j] - Mv[8 + j] - Mv[12 + j];
        }
        sOut[oc * 36 + (2 * ty) * 6 + 2 * tx]         = t0[0] + t0[1] + t0[2] + bs;
        sOut[oc * 36 + (2 * ty) * 6 + 2 * tx + 1]     = t0[1] - t0[2] - t0[3] + bs;
        sOut[oc * 36 + (2 * ty + 1) * 6 + 2 * tx]     = t1[0] + t1[1] + t1[2] + bs;
        sOut[oc * 36 + (2 * ty + 1) * 6 + 2 * tx + 1] = t1[1] - t1[2] - t1[3] + bs;
    }
    __syncthreads();
    float* dst = g_zf[b] + (size_t)img * 256 * 36;
#pragma unroll
    for (int k = 0; k < 36; k++) {
        int f = k * 256 + threadIdx.x;
        dst[f] = sOut[f];
    }
}

// ================ fused inverse transform (x) + depthwise xcorr ==============
#define SXSTR 901
#define IX_SXF_BYTES (16 * SXSTR * 4)               // 57664
#define IX_SMEM (IX_SXF_BYTES + 16 * 36 * 4 + 64)   // 60032

__global__ __launch_bounds__(256)
void inv_xcorr(float* __restrict__ out) {
    extern __shared__ __align__(16) char ism[];
    float* sxf = (float*)ism;                        // [16][SXSTR]
    float* sz  = (float*)(ism + IX_SXF_BYTES);       // [16][36]
    float* sB  = (float*)(ism + IX_SXF_BYTES + 16 * 36 * 4);

    const int ocq = blockIdx.x, img = blockIdx.y, b = blockIdx.z;
    const int tid = threadIdx.x;
    const int ocb = ocq * 16;

    if (tid < 16) sB[tid] = g_bias[1 + 2 * b][ocb + tid];
#pragma unroll
    for (int k = 0; k < 3; k++) {
        int id = k * 256 + tid;
        if (id < 576) {
            int oc = id / 36, q = id - oc * 36;
            sz[oc * 36 + q] = g_zf[b][((size_t)img * 256 + ocb + oc) * 36 + q];
        }
    }
    __syncthreads();

    const float* Mb = g_M[b] + (size_t)img * 225 * 4096 + ocb;
#pragma unroll
    for (int k = 0; k < 15; k++) {
        int it = k * 256 + tid;
        if (it < 3600) {
            int oc = it & 15, tile = it >> 4;
            int ty = tile / 15, tx = tile - ty * 15;
            const float* mp = Mb + (size_t)tile * 4096 + oc;
            float Mv[16];
#pragma unroll
            for (int pos = 0; pos < 16; pos++) Mv[pos] = mp[pos * 256];
            float t0[4], t1[4];
#pragma unroll
            for (int j = 0; j < 4; j++) {
                t0[j] = Mv[j] + Mv[4 + j] + Mv[8 + j];
                t1[j] = Mv[4 + j] - Mv[8 + j] - Mv[12 + j];
            }
            float bs = sB[oc];
            float* so = sxf + oc * SXSTR + (2 * ty) * 30 + 2 * tx;
            so[0]  = t0[0] + t0[1] + t0[2] + bs;
            so[1]  = t0[1] - t0[2] - t0[3] + bs;
            so[30] = t1[0] + t1[1] + t1[2] + bs;
            so[31] = t1[1] - t1[2] - t1[3] + bs;
        }
    }
    __syncthreads();

    float* ob = out + (size_t)b * OSZ + ((size_t)img * 256 + ocb) * 625;
#pragma unroll 4
    for (int k = 0; k < 40; k++) {
        int it = k * 256 + tid;
        if (it < 10000) {
            int oc = it / 625, pix = it - oc * 625;
            int oy = pix / 25, ox = pix - oy * 25;
            const float* xp = sxf + oc * SXSTR + oy * 30 + ox;
            const float* zp = sz + oc * 36;
            float s = 0.f;
#pragma unroll
            for (int u = 0; u < 6; u++)
#pragma unroll
                for (int v = 0; v < 6; v++)
                    s = fmaf(zp[u * 6 + v], xp[u * 30 + v], s);
            ob[(size_t)oc * 625 + pix] = s;
        }
    }
}

// ============================ launch =========================================
extern "C" void kernel_launch(void* const* d_in, const int* in_sizes, int n_in,
                              void* d_out, int out_size) {
    const float* z = (const float*)d_in[0];
    const float* x = (const float*)d_in[1];

    PrepArgs pa;
    for (int p = 0; p < 4; p++) {
        pa.w[p] = (const float*)d_in[2 + p * 5 + 0];
        pa.g[p] = (const float*)d_in[2 + p * 5 + 1];
        pa.b[p] = (const float*)d_in[2 + p * 5 + 2];
        pa.m[p] = (const float*)d_in[2 + p * 5 + 3];
        pa.v[p] = (const float*)d_in[2 + p * 5 + 4];
    }

    cudaFuncSetAttribute(wino_gemm,
                         cudaFuncAttributeMaxDynamicSharedMemorySize, GEMM_SMEM);
    cudaFuncSetAttribute(wino_gemm,
                         cudaFuncAttributePreferredSharedMemoryCarveout, 100);
    cudaFuncSetAttribute(xform_x,
                         cudaFuncAttributeMaxDynamicSharedMemorySize, XF_SMEM);
    cudaFuncSetAttribute(inv_xcorr,
                         cudaFuncAttributeMaxDynamicSharedMemorySize, IX_SMEM);

    prep_kernel<<<1024, 256>>>(pa);
    xform_x<<<dim3(32, 4, 15), 256, XF_SMEM>>>(x);
    xform_z<<<dim3(32, 32), 128>>>(z);
    wino_gemm<<<3840, 256, GEMM_SMEM>>>();
    inv_z<<<dim3(32, 2), 256>>>();
    inv_xcorr<<<dim3(16, 32, 2), 256, IX_SMEM>>>((float*)d_out);
}

// round 13
// speedup vs baseline: 1.0659x; 1.0659x over previous
#include <cuda_runtime.h>
#include <cuda_fp16.h>
#include <cstdint>

#define CIN 256
#define COUT 256
#define NB 32
#define ZSZ (NB * COUT * 36)
#define OSZ (NB * COUT * 625)

// Winograd tile counts: x: 15x15*32 = 7200 (pad 7296 = 228*32), z: 288 (pad 384)
#define NTX 7296
#define NTZ 384
#define VSX ((size_t)NTX * 512)
#define VSZ ((size_t)NTZ * 512)

__device__ __align__(16) __half g_wU[4][16 * 256 * 256]; // [path][(pos*256+oc)*256 + cin]
__device__ float g_bias[4][COUT];
__device__ __align__(16) __half g_V[16 * NTX * 512];     // [pos][tile][comp*256+cin]
__device__ __align__(16) __half g_Vz[16 * NTZ * 512];
__device__ float g_M[2][(size_t)NTX * 16 * 256];         // [branch][tile][pos][oc]
__device__ float g_Mz[2][(size_t)NTZ * 16 * 256];
__device__ float g_zf[2][ZSZ];

struct PrepArgs {
    const float* w[4];
    const float* g[4];
    const float* b[4];
    const float* m[4];
    const float* v[4];
};

// ============================ helpers ========================================
__device__ __forceinline__ uint32_t smem_u32(const void* p) {
    uint32_t a;
    asm("{ .reg .u64 t; cvta.to.shared.u64 t, %1; cvt.u32.u64 %0, t; }"
        : "=r"(a) : "l"(p));
    return a;
}
__device__ __forceinline__ void cp16(uint32_t dst, const void* src) {
    asm volatile("cp.async.cg.shared.global [%0], [%1], 16;" :: "r"(dst), "l"(src));
}
__device__ __forceinline__ void cp_commit() {
    asm volatile("cp.async.commit_group;" ::: "memory");
}
template <int N>
__device__ __forceinline__ void cp_wait() {
    asm volatile("cp.async.wait_group %0;" :: "n"(N) : "memory");
}

#define LDSM4(r, addr)                                                         \
    asm volatile("ldmatrix.sync.aligned.m8n8.x4.shared.b16 {%0,%1,%2,%3},[%4];"\
        : "=r"((r)[0]), "=r"((r)[1]), "=r"((r)[2]), "=r"((r)[3]) : "r"(addr))

#define MMA(d, a, b0, b1)                                                      \
    asm volatile("mma.sync.aligned.m16n8k16.row.col.f32.f16.f16.f32 "          \
        "{%0,%1,%2,%3}, {%4,%5,%6,%7}, {%8,%9}, {%0,%1,%2,%3};"                \
        : "+f"((d)[0]), "+f"((d)[1]), "+f"((d)[2]), "+f"((d)[3])               \
        : "r"((a)[0]), "r"((a)[1]), "r"((a)[2]), "r"((a)[3]),                  \
          "r"(b0), "r"(b1))

__device__ __forceinline__ void hsplit(float v, __half& hi, __half& lo) {
    hi = __float2half_rn(v);
    lo = __float2half_rn(v - __half2float(hi));
}

// ============================ prep: weight transform =========================
__global__ void prep_kernel(PrepArgs a) {
    int i = blockIdx.x * blockDim.x + threadIdx.x;       // 262144 items
    int path = i >> 16;
    int oc   = (i >> 8) & 255;
    int cin  = i & 255;
    float inv = a.g[path][oc] * rsqrtf(a.v[path][oc] + 1e-5f);
    const float* wp = a.w[path] + oc * 2304 + cin * 9;
    float w[3][3];
#pragma unroll
    for (int r = 0; r < 3; r++)
#pragma unroll
        for (int c = 0; c < 3; c++) w[r][c] = wp[r * 3 + c] * inv;

    float T[4][3];
#pragma unroll
    for (int j = 0; j < 3; j++) {
        T[0][j] = w[0][j];
        T[1][j] = 0.5f * (w[0][j] + w[1][j] + w[2][j]);
        T[2][j] = 0.5f * (w[0][j] - w[1][j] + w[2][j]);
        T[3][j] = w[2][j];
    }
#pragma unroll
    for (int r = 0; r < 4; r++) {
        float U[4];
        U[0] = T[r][0];
        U[1] = 0.5f * (T[r][0] + T[r][1] + T[r][2]);
        U[2] = 0.5f * (T[r][0] - T[r][1] + T[r][2]);
        U[3] = T[r][2];
#pragma unroll
        for (int c = 0; c < 4; c++)
            g_wU[path][((size_t)((r * 4 + c) * 256 + oc)) * 256 + cin] =
                __float2half_rn(U[c]);
    }
    if (i < 1024) {
        int p2 = i >> 8, oc2 = i & 255;
        float inv2 = a.g[p2][oc2] * rsqrtf(a.v[p2][oc2] + 1e-5f);
        g_bias[p2][oc2] = a.b[p2][oc2] - a.m[p2][oc2] * inv2;
    }
}

// ============================ input transforms ===============================
__device__ __forceinline__ void wino_fwd(const float d[4][4], float V[4][4]) {
    float t[4][4];
#pragma unroll
    for (int j = 0; j < 4; j++) {
        t[0][j] = d[0][j] - d[2][j];
        t[1][j] = d[1][j] + d[2][j];
        t[2][j] = d[2][j] - d[1][j];
        t[3][j] = d[1][j] - d[3][j];
    }
#pragma unroll
    for (int i = 0; i < 4; i++) {
        V[i][0] = t[i][0] - t[i][2];
        V[i][1] = t[i][1] + t[i][2];
        V[i][2] = t[i][2] - t[i][1];
        V[i][3] = t[i][1] - t[i][3];
    }
}

#define SDSTR 129
#define XF_SD_BYTES (64 * SDSTR * 4)                 // 33024
#define XF_SV_OFF   XF_SD_BYTES
#define XF_SMEM (XF_SD_BYTES + 15 * 16 * 2 * 64 * 2) // 94464

__global__ __launch_bounds__(256)
void xform_x(const float* __restrict__ x) {
    extern __shared__ __align__(16) char xsm[];
    float* sd = (float*)xsm;
    __half* sV = (__half*)(xsm + XF_SV_OFF);         // [tile][pos][comp][64]
    const int img = blockIdx.x, cg = blockIdx.y, ty = blockIdx.z;
    const int tid = threadIdx.x;
    const int c0 = cg * 64;
    const float* src = x + ((size_t)img * 256 + c0) * 1024 + 2 * ty * 32;

#pragma unroll
    for (int k = 0; k < 32; k++) {
        int id = k * 256 + tid;
        int c = id >> 7, rc = id & 127;
        sd[c * SDSTR + rc] = src[(size_t)c * 1024 + rc];
    }
    __syncthreads();

#pragma unroll
    for (int k = 0; k < 4; k++) {
        int id = k * 256 + tid;
        if (id < 960) {
            int tx = id >> 6, c = id & 63;
            const float* p = sd + c * SDSTR + 2 * tx;
            float d[4][4], V[4][4];
#pragma unroll
            for (int i = 0; i < 4; i++)
#pragma unroll
                for (int j = 0; j < 4; j++) d[i][j] = p[i * 32 + j];
            wino_fwd(d, V);
#pragma unroll
            for (int i = 0; i < 4; i++)
#pragma unroll
                for (int j = 0; j < 4; j++) {
                    __half hi, lo;
                    hsplit(V[i][j], hi, lo);
                    int pb = (tx * 16 + (i * 4 + j)) * 128;
                    sV[pb + c]      = hi;
                    sV[pb + 64 + c] = lo;
                }
        }
    }
    __syncthreads();

#pragma unroll
    for (int k = 0; k < 15; k++) {                   // exactly 3840 uint4
        int id = k * 256 + tid;
        int q    = id & 7;
        int comp = (id >> 3) & 1;
        int pos  = (id >> 4) & 15;
        int tile = id >> 8;
        uint4 v = *(const uint4*)(sV + ((tile * 16 + pos) * 2 + comp) * 64 + q * 8);
        *(uint4*)(g_V + (size_t)pos * VSX +
                  ((size_t)img * 225 + ty * 15 + tile) * 512 +
                  comp * 256 + c0 + q * 8) = v;
    }
}

__global__ __launch_bounds__(128)
void xform_z(const float* __restrict__ z) {
    __shared__ float sd[8][64];
    __shared__ __align__(16) __half sVz[9][16][2][8];
    const int img = blockIdx.x, cg = blockIdx.y, tid = threadIdx.x;
    const float* src = z + ((size_t)img * 256 + cg * 8) * 64;
#pragma unroll
    for (int k = 0; k < 4; k++) {
        int lin = k * 128 + tid;
        sd[lin >> 6][lin & 63] = src[lin];
    }
    __syncthreads();
    if (tid < 72) {
        int tl = tid >> 3, c = tid & 7;
        int ty = tl / 3, tx = tl - ty * 3;
        float d[4][4], V[4][4];
#pragma unroll
        for (int i = 0; i < 4; i++)
#pragma unroll
            for (int j = 0; j < 4; j++)
                d[i][j] = sd[c][(2 * ty + i) * 8 + 2 * tx + j];
        wino_fwd(d, V);
#pragma unroll
        for (int i = 0; i < 4; i++)
#pragma unroll
            for (int j = 0; j < 4; j++) {
                __half hi, lo;
                hsplit(V[i][j], hi, lo);
                sVz[tl][i * 4 + j][0][c] = hi;
                sVz[tl][i * 4 + j][1][c] = lo;
            }
    }
    __syncthreads();
#pragma unroll
    for (int k = 0; k < 3; k++) {
        int cid = k * 128 + tid;
        if (cid < 288) {
            int tl = cid >> 5, pos = (cid >> 1) & 15, comp = cid & 1;
            uint4 val = *(const uint4*)&sVz[tl][pos][comp][0];
            *(uint4*)(g_Vz + (size_t)pos * VSZ +
                      ((size_t)img * 9 + tl) * 512 + comp * 256 + cg * 8) = val;
        }
    }
}

// ============================ batched GEMM ===================================
// D[128 tile, 128 oc] = V[128,256] * U[128,256]^T, 2-term fp16 A split.
// 128 threads, 4 warps (2x2), warp tile 64x64. K-chunk 64 (4 chunks).
// Block groups of 4 (b,o)-combos share the same V slice (L2 reuse).
#define ASTR 272u                  // row: 64 hi (128B) | 64 lo (128B) | 16 pad
#define ABUF (128u * ASTR)         // 34816
#define BSTR 144u                  // row: 64 cin (128B) | 16 pad
#define BBUF (128u * BSTR)         // 18432
#define BOFF (2u * ABUF)           // 69632
#define GEMM_SMEM (BOFF + 2u * BBUF)   // 106496

__global__ __launch_bounds__(128, 2)
void wino_gemm() {
    extern __shared__ __align__(16) char smem[];
    const int tid = threadIdx.x, lid = tid & 31, wid = tid >> 5;
    const int warp_m = wid >> 1, warp_n = wid & 1;
    const uint32_t sBu = smem_u32(smem);

    const int bid = blockIdx.x;
    const __half *vsrc, *wsrc;
    float* mdst;
    if (bid < 3648) {
        int combo = bid & 3, b = combo >> 1, o = combo & 1;
        int group = bid >> 2;              // 0..911
        int p = group / 57, mt = group - p * 57;
        vsrc = g_V + (size_t)p * VSX + (size_t)mt * 128 * 512;
        wsrc = g_wU[1 + 2 * b] + ((size_t)(p * 256) + o * 128) * 256;
        mdst = g_M[b] + ((size_t)mt * 128) * 4096 + p * 256 + o * 128;
    } else {
        int zb = bid - 3648;               // 0..191
        int combo = zb & 3, b = combo >> 1, o = combo & 1;
        int group = zb >> 2;               // 0..47
        int p = group / 3, mt = group - p * 3;
        vsrc = g_Vz + (size_t)p * VSZ + (size_t)mt * 128 * 512;
        wsrc = g_wU[2 * b] + ((size_t)(p * 256) + o * 128) * 256;
        mdst = g_Mz[b] + ((size_t)mt * 128) * 4096 + p * 256 + o * 128;
    }

    float acc[4][8][4];
#pragma unroll
    for (int t = 0; t < 4; t++)
#pragma unroll
        for (int j = 0; j < 8; j++)
#pragma unroll
            for (int e = 0; e < 4; e++) acc[t][j][e] = 0.f;

    auto copyAB = [&](int g) {
        const int buf = g & 1, c0 = g * 64;
#pragma unroll
        for (int k = 0; k < 16; k++) {               // A: 2048 cp16 (hi+lo)
            int id = tid + k * 128;
            int row = id >> 4, part = id & 15, comp = part >> 3, kq = part & 7;
            cp16(sBu + buf * ABUF + row * ASTR + comp * 128 + kq * 16,
                 vsrc + (size_t)row * 512 + comp * 256 + c0 + kq * 8);
        }
#pragma unroll
        for (int k = 0; k < 8; k++) {                // B: 1024 cp16
            int id = tid + k * 128;
            int row = id >> 3, part = id & 7;
            cp16(sBu + BOFF + buf * BBUF + row * BSTR + part * 16,
                 wsrc + (size_t)row * 256 + c0 + part * 8);
        }
        cp_commit();
    };

    copyAB(0);
#pragma unroll 1
    for (int g = 0; g < 4; g++) {
        const int buf = g & 1;
        cp_wait<0>();      // data for chunk g has landed
        __syncthreads();   // everyone done consuming the other buffer
        if (g + 1 < 4) copyAB(g + 1);   // overlaps with compute below

        uint32_t aaddr[4], baddr[4];
#pragma unroll
        for (int t = 0; t < 4; t++) {
            int m = warp_m * 64 + t * 16 + (lid & 7) + ((lid >> 3) & 1) * 8;
            aaddr[t] = sBu + buf * ABUF + m * ASTR + ((lid >> 4) << 4);
        }
#pragma unroll
        for (int j = 0; j < 4; j++) {
            int n = warp_n * 64 + j * 16 + (lid & 7) + (lid >> 4) * 8;
            baddr[j] = sBu + BOFF + buf * BBUF + n * BSTR + (((lid >> 3) & 1) << 4);
        }

#pragma unroll
        for (int ks = 0; ks < 4; ks++) {
            uint32_t ah[4][4], al[4][4], bq[4][4];
#pragma unroll
            for (int t = 0; t < 4; t++) LDSM4(ah[t], aaddr[t] + ks * 32);
#pragma unroll
            for (int t = 0; t < 4; t++) LDSM4(al[t], aaddr[t] + ks * 32 + 128);
#pragma unroll
            for (int j = 0; j < 4; j++) LDSM4(bq[j], baddr[j] + ks * 32);
            // hi*B
#pragma unroll
            for (int t = 0; t < 4; t++)
#pragma unroll
                for (int j = 0; j < 4; j++) {
                    MMA(acc[t][2 * j],     ah[t], bq[j][0], bq[j][1]);
                    MMA(acc[t][2 * j + 1], ah[t], bq[j][2], bq[j][3]);
                }
            // lo*B
#pragma unroll
            for (int t = 0; t < 4; t++)
#pragma unroll
                for (int j = 0; j < 4; j++) {
                    MMA(acc[t][2 * j],     al[t], bq[j][0], bq[j][1]);
                    MMA(acc[t][2 * j + 1], al[t], bq[j][2], bq[j][3]);
                }
        }
    }

    // epilogue: [tile][pos][oc] stores; tile stride 4096 floats
#pragma unroll
    for (int t = 0; t < 4; t++) {
        int r = warp_m * 64 + t * 16 + (lid >> 2);
#pragma unroll
        for (int jj = 0; jj < 8; jj++) {
            int c = warp_n * 64 + (jj >> 1) * 16 + (jj & 1) * 8 + (lid & 3) * 2;
            float* base = mdst + (size_t)r * 4096 + c;
            *(float2*)base = make_float2(acc[t][jj][0], acc[t][jj][1]);
            *(float2*)(base + (size_t)8 * 4096) = make_float2(acc[t][jj][2], acc[t][jj][3]);
        }
    }
}

// ============================ inverse transform: z ===========================
__global__ __launch_bounds__(256)
void inv_z() {
    __shared__ float sOut[256 * 36];
    const int img = blockIdx.x, b = blockIdx.y;
    const int oc = threadIdx.x;
    const float bs = g_bias[2 * b][oc];
    const float* Mb = g_Mz[b];
#pragma unroll
    for (int t = 0; t < 9; t++) {
        int ty = t / 3, tx = t - ty * 3;
        const float* mp = Mb + ((size_t)img * 9 + t) * 4096 + oc;
        float Mv[16];
#pragma unroll
        for (int pos = 0; pos < 16; pos++) Mv[pos] = mp[pos * 256];
        float t0[4], t1[4];
#pragma unroll
        for (int j = 0; j < 4; j++) {
            t0[j] = Mv[j] + Mv[4 + j] + Mv[8 + j];
            t1[j] = Mv[4 + j] - Mv[8 + j] - Mv[12 + j];
        }
        sOut[oc * 36 + (2 * ty) * 6 + 2 * tx]         = t0[0] + t0[1] + t0[2] + bs;
        sOut[oc * 36 + (2 * ty) * 6 + 2 * tx + 1]     = t0[1] - t0[2] - t0[3] + bs;
        sOut[oc * 36 + (2 * ty + 1) * 6 + 2 * tx]     = t1[0] + t1[1] + t1[2] + bs;
        sOut[oc * 36 + (2 * ty + 1) * 6 + 2 * tx + 1] = t1[1] - t1[2] - t1[3] + bs;
    }
    __syncthreads();
    float* dst = g_zf[b] + (size_t)img * 256 * 36;
#pragma unroll
    for (int k = 0; k < 36; k++) {
        int f = k * 256 + threadIdx.x;
        dst[f] = sOut[f];
    }
}

// ================ fused inverse transform (x) + depthwise xcorr ==============
#define SXSTR 901
#define IX_SXF_BYTES (16 * SXSTR * 4)               // 57664
#define IX_SMEM (IX_SXF_BYTES + 16 * 36 * 4 + 64)   // 60032

__global__ __launch_bounds__(256)
void inv_xcorr(float* __restrict__ out) {
    extern __shared__ __align__(16) char ism[];
    float* sxf = (float*)ism;                        // [16][SXSTR]
    float* sz  = (float*)(ism + IX_SXF_BYTES);       // [16][36]
    float* sB  = (float*)(ism + IX_SXF_BYTES + 16 * 36 * 4);

    const int ocq = blockIdx.x, img = blockIdx.y, b = blockIdx.z;
    const int tid = threadIdx.x;
    const int ocb = ocq * 16;

    if (tid < 16) sB[tid] = g_bias[1 + 2 * b][ocb + tid];
#pragma unroll
    for (int k = 0; k < 3; k++) {
        int id = k * 256 + tid;
        if (id < 576) {
            int oc = id / 36, q = id - oc * 36;
            sz[oc * 36 + q] = g_zf[b][((size_t)img * 256 + ocb + oc) * 36 + q];
        }
    }
    __syncthreads();

    const float* Mb = g_M[b] + (size_t)img * 225 * 4096 + ocb;
#pragma unroll
    for (int k = 0; k < 15; k++) {
        int it = k * 256 + tid;
        if (it < 3600) {
            int oc = it & 15, tile = it >> 4;
            int ty = tile / 15, tx = tile - ty * 15;
            const float* mp = Mb + (size_t)tile * 4096 + oc;
            float Mv[16];
#pragma unroll
            for (int pos = 0; pos < 16; pos++) Mv[pos] = mp[pos * 256];
            float t0[4], t1[4];
#pragma unroll
            for (int j = 0; j < 4; j++) {
                t0[j] = Mv[j] + Mv[4 + j] + Mv[8 + j];
                t1[j] = Mv[4 + j] - Mv[8 + j] - Mv[12 + j];
            }
            float bs = sB[oc];
            float* so = sxf + oc * SXSTR + (2 * ty) * 30 + 2 * tx;
            so[0]  = t0[0] + t0[1] + t0[2] + bs;
            so[1]  = t0[1] - t0[2] - t0[3] + bs;
            so[30] = t1[0] + t1[1] + t1[2] + bs;
            so[31] = t1[1] - t1[2] - t1[3] + bs;
        }
    }
    __syncthreads();

    float* ob = out + (size_t)b * OSZ + ((size_t)img * 256 + ocb) * 625;
#pragma unroll 4
    for (int k = 0; k < 40; k++) {
        int it = k * 256 + tid;
        if (it < 10000) {
            int oc = it / 625, pix = it - oc * 625;
            int oy = pix / 25, ox = pix - oy * 25;
            const float* xp = sxf + oc * SXSTR + oy * 30 + ox;
            const float* zp = sz + oc * 36;
            float s = 0.f;
#pragma unroll
            for (int u = 0; u < 6; u++)
#pragma unroll
                for (int v = 0; v < 6; v++)
                    s = fmaf(zp[u * 6 + v], xp[u * 30 + v], s);
            ob[(size_t)oc * 625 + pix] = s;
        }
    }
}

// ============================ launch =========================================
extern "C" void kernel_launch(void* const* d_in, const int* in_sizes, int n_in,
                              void* d_out, int out_size) {
    const float* z = (const float*)d_in[0];
    const float* x = (const float*)d_in[1];

    PrepArgs pa;
    for (int p = 0; p < 4; p++) {
        pa.w[p] = (const float*)d_in[2 + p * 5 + 0];
        pa.g[p] = (const float*)d_in[2 + p * 5 + 1];
        pa.b[p] = (const float*)d_in[2 + p * 5 + 2];
        pa.m[p] = (const float*)d_in[2 + p * 5 + 3];
        pa.v[p] = (const float*)d_in[2 + p * 5 + 4];
    }

    cudaFuncSetAttribute(wino_gemm,
                         cudaFuncAttributeMaxDynamicSharedMemorySize, GEMM_SMEM);
    cudaFuncSetAttribute(wino_gemm,
                         cudaFuncAttributePreferredSharedMemoryCarveout, 100);
    cudaFuncSetAttribute(xform_x,
                         cudaFuncAttributeMaxDynamicSharedMemorySize, XF_SMEM);
    cudaFuncSetAttribute(inv_xcorr,
                         cudaFuncAttributeMaxDynamicSharedMemorySize, IX_SMEM);

    prep_kernel<<<1024, 256>>>(pa);
    xform_x<<<dim3(32, 4, 15), 256, XF_SMEM>>>(x);
    xform_z<<<dim3(32, 32), 128>>>(z);
    wino_gemm<<<3840, 128, GEMM_SMEM>>>();
    inv_z<<<dim3(32, 2), 256>>>();
    inv_xcorr<<<dim3(16, 32, 2), 256, IX_SMEM>>>((float*)d_out);
}

// round 14
// speedup vs baseline: 1.2217x; 1.1462x over previous
#include <cuda_runtime.h>
#include <cuda_fp16.h>
#include <cstdint>

#define CIN 256
#define COUT 256
#define NB 32
#define OSZ (NB * COUT * 625)

// Winograd tile counts: x: 15x15*32 = 7200 (pad 7296 = 228*32), z: 288 (pad 384)
#define NTX 7296
#define NTZ 384
#define VSX ((size_t)NTX * 256)
#define VSZ ((size_t)NTZ * 256)

__device__ __align__(16) __half g_wU[4][16 * 256 * 512]; // [path][(pos*256+oc)*512 + comp*256+cin] hi/lo
__device__ float g_bias[4][COUT];
__device__ __align__(16) __half g_V[16 * NTX * 256];     // [pos][tile][cin] single fp16
__device__ __align__(16) __half g_Vz[16 * NTZ * 256];
__device__ float g_M[2][(size_t)NTX * 16 * 256];         // [branch][tile][pos][oc]
__device__ float g_Mz[2][(size_t)NTZ * 16 * 256];

struct PrepArgs {
    const float* w[4];
    const float* g[4];
    const float* b[4];
    const float* m[4];
    const float* v[4];
};

// ============================ helpers ========================================
__device__ __forceinline__ uint32_t smem_u32(const void* p) {
    uint32_t a;
    asm("{ .reg .u64 t; cvta.to.shared.u64 t, %1; cvt.u32.u64 %0, t; }"
        : "=r"(a) : "l"(p));
    return a;
}
__device__ __forceinline__ void cp16(uint32_t dst, const void* src) {
    asm volatile("cp.async.cg.shared.global [%0], [%1], 16;" :: "r"(dst), "l"(src));
}
__device__ __forceinline__ void cp_commit() {
    asm volatile("cp.async.commit_group;" ::: "memory");
}
template <int N>
__device__ __forceinline__ void cp_wait() {
    asm volatile("cp.async.wait_group %0;" :: "n"(N) : "memory");
}

#define LDSM4(r, addr)                                                         \
    asm volatile("ldmatrix.sync.aligned.m8n8.x4.shared.b16 {%0,%1,%2,%3},[%4];"\
        : "=r"((r)[0]), "=r"((r)[1]), "=r"((r)[2]), "=r"((r)[3]) : "r"(addr))

#define MMA(d, a, b0, b1)                                                      \
    asm volatile("mma.sync.aligned.m16n8k16.row.col.f32.f16.f16.f32 "          \
        "{%0,%1,%2,%3}, {%4,%5,%6,%7}, {%8,%9}, {%0,%1,%2,%3};"                \
        : "+f"((d)[0]), "+f"((d)[1]), "+f"((d)[2]), "+f"((d)[3])               \
        : "r"((a)[0]), "r"((a)[1]), "r"((a)[2]), "r"((a)[3]),                  \
          "r"(b0), "r"(b1))

__device__ __forceinline__ void hsplit(float v, __half& hi, __half& lo) {
    hi = __float2half_rn(v);
    lo = __float2half_rn(v - __half2float(hi));
}

__device__ __forceinline__ void wino_fwd(const float d[4][4], float V[4][4]) {
    float t[4][4];
#pragma unroll
    for (int j = 0; j < 4; j++) {
        t[0][j] = d[0][j] - d[2][j];
        t[1][j] = d[1][j] + d[2][j];
        t[2][j] = d[2][j] - d[1][j];
        t[3][j] = d[1][j] - d[3][j];
    }
#pragma unroll
    for (int i = 0; i < 4; i++) {
        V[i][0] = t[i][0] - t[i][2];
        V[i][1] = t[i][1] + t[i][2];
        V[i][2] = t[i][2] - t[i][1];
        V[i][3] = t[i][1] - t[i][3];
    }
}

// =============== fused: weight transform (prep) + x input transform ==========
// blocks 0..1919: xform_x (ty = bid/128, cg = (bid%128)/32, img = bid%32)
// blocks 1920..2943: prep (1024 blocks x 256 items)
#define SDSTR 129
#define XF_SD_BYTES (64 * SDSTR * 4)                 // 33024
#define XF_SMEM (XF_SD_BYTES + 15 * 16 * 64 * 2)     // 63744

__global__ __launch_bounds__(256)
void prep_xform(const float* __restrict__ x, PrepArgs a) {
    const int tid = threadIdx.x;
    if (blockIdx.x >= 1920) {
        // -------- prep: U = G g G^T, BN folded, hi/lo fp16 ------------------
        int i = (blockIdx.x - 1920) * 256 + tid;     // 262144 items
        int path = i >> 16;
        int oc   = (i >> 8) & 255;
        int cin  = i & 255;
        float inv = a.g[path][oc] * rsqrtf(a.v[path][oc] + 1e-5f);
        const float* wp = a.w[path] + oc * 2304 + cin * 9;
        float w[3][3];
#pragma unroll
        for (int r = 0; r < 3; r++)
#pragma unroll
            for (int c = 0; c < 3; c++) w[r][c] = wp[r * 3 + c] * inv;
        float T[4][3];
#pragma unroll
        for (int j = 0; j < 3; j++) {
            T[0][j] = w[0][j];
            T[1][j] = 0.5f * (w[0][j] + w[1][j] + w[2][j]);
            T[2][j] = 0.5f * (w[0][j] - w[1][j] + w[2][j]);
            T[3][j] = w[2][j];
        }
#pragma unroll
        for (int r = 0; r < 4; r++) {
            float U[4];
            U[0] = T[r][0];
            U[1] = 0.5f * (T[r][0] + T[r][1] + T[r][2]);
            U[2] = 0.5f * (T[r][0] - T[r][1] + T[r][2]);
            U[3] = T[r][2];
#pragma unroll
            for (int c = 0; c < 4; c++) {
                __half hi, lo;
                hsplit(U[c], hi, lo);
                size_t base = ((size_t)((r * 4 + c) * 256 + oc)) * 512 + cin;
                g_wU[path][base]       = hi;
                g_wU[path][base + 256] = lo;
            }
        }
        if (i < 1024) {
            int p2 = i >> 8, oc2 = i & 255;
            float inv2 = a.g[p2][oc2] * rsqrtf(a.v[p2][oc2] + 1e-5f);
            g_bias[p2][oc2] = a.b[p2][oc2] - a.m[p2][oc2] * inv2;
        }
        return;
    }

    // -------- xform_x: V = B^T d B, single fp16 ------------------------------
    extern __shared__ __align__(16) char xsm[];
    float* sd = (float*)xsm;
    __half* sV = (__half*)(xsm + XF_SD_BYTES);       // [tile][pos][64]
    const int bid = blockIdx.x;
    const int ty  = bid >> 7;
    const int cg  = (bid >> 5) & 3;
    const int img = bid & 31;
    const int c0 = cg * 64;
    const float* src = x + ((size_t)img * 256 + c0) * 1024 + 2 * ty * 32;

#pragma unroll
    for (int k = 0; k < 32; k++) {
        int id = k * 256 + tid;
        int c = id >> 7, rc = id & 127;
        sd[c * SDSTR + rc] = src[(size_t)c * 1024 + rc];
    }
    __syncthreads();

#pragma unroll
    for (int k = 0; k < 4; k++) {
        int id = k * 256 + tid;
        if (id < 960) {
            int tx = id >> 6, c = id & 63;
            const float* p = sd + c * SDSTR + 2 * tx;
            float d[4][4], V[4][4];
#pragma unroll
            for (int i = 0; i < 4; i++)
#pragma unroll
                for (int j = 0; j < 4; j++) d[i][j] = p[i * 32 + j];
            wino_fwd(d, V);
#pragma unroll
            for (int i = 0; i < 4; i++)
#pragma unroll
                for (int j = 0; j < 4; j++)
                    sV[(tx * 16 + (i * 4 + j)) * 64 + c] = __float2half_rn(V[i][j]);
        }
    }
    __syncthreads();

#pragma unroll
    for (int k = 0; k < 8; k++) {                    // 1920 uint4
        int id = k * 256 + tid;
        if (id < 1920) {
            int q    = id & 7;
            int pos  = (id >> 3) & 15;
            int tile = id >> 7;
            uint4 v = *(const uint4*)(sV + (tile * 16 + pos) * 64 + q * 8);
            *(uint4*)(g_V + (size_t)pos * VSX +
                      ((size_t)img * 225 + ty * 15 + tile) * 256 + c0 + q * 8) = v;
        }
    }
}

__global__ __launch_bounds__(128)
void xform_z(const float* __restrict__ z) {
    __shared__ float sd[8][64];
    __shared__ __align__(16) __half sVz[9][16][8];
    const int img = blockIdx.x, cg = blockIdx.y, tid = threadIdx.x;
    const float* src = z + ((size_t)img * 256 + cg * 8) * 64;
#pragma unroll
    for (int k = 0; k < 4; k++) {
        int lin = k * 128 + tid;
        sd[lin >> 6][lin & 63] = src[lin];
    }
    __syncthreads();
    if (tid < 72) {
        int tl = tid >> 3, c = tid & 7;
        int ty = tl / 3, tx = tl - ty * 3;
        float d[4][4], V[4][4];
#pragma unroll
        for (int i = 0; i < 4; i++)
#pragma unroll
            for (int j = 0; j < 4; j++)
                d[i][j] = sd[c][(2 * ty + i) * 8 + 2 * tx + j];
        wino_fwd(d, V);
#pragma unroll
        for (int i = 0; i < 4; i++)
#pragma unroll
            for (int j = 0; j < 4; j++)
                sVz[tl][i * 4 + j][c] = __float2half_rn(V[i][j]);
    }
    __syncthreads();
#pragma unroll
    for (int k = 0; k < 2; k++) {
        int cid = k * 128 + tid;                     // 144 uint4
        if (cid < 144) {
            int pos = cid & 15, tl = cid >> 4;
            uint4 val = *(const uint4*)&sVz[tl][pos][0];
            *(uint4*)(g_Vz + (size_t)pos * VSZ +
                      ((size_t)img * 9 + tl) * 256 + cg * 8) = val;
        }
    }
}

// ============================ batched GEMM ===================================
// D[128 tile, 128 oc] = V[128,256] * U[128,256]^T.
// A (V) single fp16; B (U) hi+lo fp16 split. K-chunk 64 (4 chunks), 4 warps.
// Block groups of 4 (b,o)-combos share the same V slice (L2 reuse).
#define ASTR 144u                  // A row: 64 cin (128B) + 16 pad
#define ABUF (128u * ASTR)         // 18432
#define BSTR 272u                  // B row: 64 hi (128B) | 64 lo (128B) | 16 pad
#define BBUF (128u * BSTR)         // 34816
#define BOFF (2u * ABUF)           // 36864
#define GEMM_SMEM (BOFF + 2u * BBUF)   // 106496

__global__ __launch_bounds__(128, 2)
void wino_gemm() {
    extern __shared__ __align__(16) char smem[];
    const int tid = threadIdx.x, lid = tid & 31, wid = tid >> 5;
    const int warp_m = wid >> 1, warp_n = wid & 1;
    const uint32_t sBu = smem_u32(smem);

    const int bid = blockIdx.x;
    const __half *vsrc, *wsrc;
    float* mdst;
    if (bid < 3648) {
        int combo = bid & 3, b = combo >> 1, o = combo & 1;
        int group = bid >> 2;              // 0..911
        int p = group / 57, mt = group - p * 57;
        vsrc = g_V + (size_t)p * VSX + (size_t)mt * 128 * 256;
        wsrc = g_wU[1 + 2 * b] + ((size_t)(p * 256) + o * 128) * 512;
        mdst = g_M[b] + ((size_t)mt * 128) * 4096 + p * 256 + o * 128;
    } else {
        int zb = bid - 3648;               // 0..191
        int combo = zb & 3, b = combo >> 1, o = combo & 1;
        int group = zb >> 2;               // 0..47
        int p = group / 3, mt = group - p * 3;
        vsrc = g_Vz + (size_t)p * VSZ + (size_t)mt * 128 * 256;
        wsrc = g_wU[2 * b] + ((size_t)(p * 256) + o * 128) * 512;
        mdst = g_Mz[b] + ((size_t)mt * 128) * 4096 + p * 256 + o * 128;
    }

    float acc[4][8][4];
#pragma unroll
    for (int t = 0; t < 4; t++)
#pragma unroll
        for (int j = 0; j < 8; j++)
#pragma unroll
            for (int e = 0; e < 4; e++) acc[t][j][e] = 0.f;

    auto copyAB = [&](int g) {
        const int buf = g & 1, c0 = g * 64;
#pragma unroll
        for (int k = 0; k < 8; k++) {                // A: 1024 cp16 (single)
            int id = tid + k * 128;
            int row = id >> 3, kq = id & 7;
            cp16(sBu + buf * ABUF + row * ASTR + kq * 16,
                 vsrc + (size_t)row * 256 + c0 + kq * 8);
        }
#pragma unroll
        for (int k = 0; k < 16; k++) {               // B: 2048 cp16 (hi+lo)
            int id = tid + k * 128;
            int row = id >> 4, part = id & 15, comp = part >> 3, kq = part & 7;
            cp16(sBu + BOFF + buf * BBUF + row * BSTR + comp * 128 + kq * 16,
                 wsrc + (size_t)row * 512 + comp * 256 + c0 + kq * 8);
        }
        cp_commit();
    };

    copyAB(0);
#pragma unroll 1
    for (int g = 0; g < 4; g++) {
        const int buf = g & 1;
        cp_wait<0>();      // data for chunk g has landed
        __syncthreads();   // everyone done consuming the other buffer
        if (g + 1 < 4) copyAB(g + 1);   // overlaps with compute below

        uint32_t aaddr[4], baddr[4];
#pragma unroll
        for (int t = 0; t < 4; t++) {
            int m = warp_m * 64 + t * 16 + (lid & 7) + ((lid >> 3) & 1) * 8;
            aaddr[t] = sBu + buf * ABUF + m * ASTR + ((lid >> 4) << 4);
        }
#pragma unroll
        for (int j = 0; j < 4; j++) {
            int n = warp_n * 64 + j * 16 + (lid & 7) + (lid >> 4) * 8;
            baddr[j] = sBu + BOFF + buf * BBUF + n * BSTR + (((lid >> 3) & 1) << 4);
        }

#pragma unroll
        for (int ks = 0; ks < 4; ks++) {
            uint32_t ah[4][4], bh[4][4], bl[4][4];
#pragma unroll
            for (int t = 0; t < 4; t++) LDSM4(ah[t], aaddr[t] + ks * 32);
#pragma unroll
            for (int j = 0; j < 4; j++) LDSM4(bh[j], baddr[j] + ks * 32);
#pragma unroll
            for (int j = 0; j < 4; j++) LDSM4(bl[j], baddr[j] + ks * 32 + 128);
            // A * B_hi
#pragma unroll
            for (int t = 0; t < 4; t++)
#pragma unroll
                for (int j = 0; j < 4; j++) {
                    MMA(acc[t][2 * j],     ah[t], bh[j][0], bh[j][1]);
                    MMA(acc[t][2 * j + 1], ah[t], bh[j][2], bh[j][3]);
                }
            // A * B_lo
#pragma unroll
            for (int t = 0; t < 4; t++)
#pragma unroll
                for (int j = 0; j < 4; j++) {
                    MMA(acc[t][2 * j],     ah[t], bl[j][0], bl[j][1]);
                    MMA(acc[t][2 * j + 1], ah[t], bl[j][2], bl[j][3]);
                }
        }
    }

    // epilogue: [tile][pos][oc] stores; tile stride 4096 floats
#pragma unroll
    for (int t = 0; t < 4; t++) {
        int r = warp_m * 64 + t * 16 + (lid >> 2);
#pragma unroll
        for (int jj = 0; jj < 8; jj++) {
            int c = warp_n * 64 + (jj >> 1) * 16 + (jj & 1) * 8 + (lid & 3) * 2;
            float* base = mdst + (size_t)r * 4096 + c;
            *(float2*)base = make_float2(acc[t][jj][0], acc[t][jj][1]);
            *(float2*)(base + (size_t)8 * 4096) = make_float2(acc[t][jj][2], acc[t][jj][3]);
        }
    }
}

// ====== fused: z inverse transform + x inverse transform + depthwise xcorr ===
// Block = (ocq of 16 oc, img, branch).
//   z-part: rebuild 16x36 zf slab from g_Mz (tiny, redundant per ocq).
//   Phase 1: rebuild 16x30x30 xf slab in smem from g_M (bias folded).
//   Phase 2: xcorr, write d_out directly.
#define SXSTR 901
#define IX_SXF_BYTES (16 * SXSTR * 4)               // 57664
#define IX_SMEM (IX_SXF_BYTES + 16 * 36 * 4)        // 59968

__global__ __launch_bounds__(256)
void inv_xcorr(float* __restrict__ out) {
    extern __shared__ __align__(16) char ism[];
    float* sxf = (float*)ism;                        // [16][SXSTR]
    float* sz  = (float*)(ism + IX_SXF_BYTES);       // [16][36]

    const int ocq = blockIdx.x, img = blockIdx.y, b = blockIdx.z;
    const int tid = threadIdx.x;
    const int ocb = ocq * 16;

    // z slab: 16 oc x 9 tiles = 144 items
    if (tid < 144) {
        int oc = tid & 15, t = tid >> 4;
        int ty = t / 3, tx = t - ty * 3;
        const float* mp = g_Mz[b] + ((size_t)(img * 9 + t)) * 4096 + ocb + oc;
        float Mv[16];
#pragma unroll
        for (int pos = 0; pos < 16; pos++) Mv[pos] = mp[pos * 256];
        float t0[4], t1[4];
#pragma unroll
        for (int j = 0; j < 4; j++) {
            t0[j] = Mv[j] + Mv[4 + j] + Mv[8 + j];
            t1[j] = Mv[4 + j] - Mv[8 + j] - Mv[12 + j];
        }
        float bz = g_bias[2 * b][ocb + oc];
        float* so = sz + oc * 36 + (2 * ty) * 6 + 2 * tx;
        so[0] = t0[0] + t0[1] + t0[2] + bz;
        so[1] = t0[1] - t0[2] - t0[3] + bz;
        so[6] = t1[0] + t1[1] + t1[2] + bz;
        so[7] = t1[1] - t1[2] - t1[3] + bz;
    }

    // Phase 1: 225 tiles x 16 oc = 3600 items
    const float* Mb = g_M[b] + (size_t)img * 225 * 4096 + ocb;
    const float* xbias = g_bias[1 + 2 * b] + ocb;
#pragma unroll
    for (int k = 0; k < 15; k++) {
        int it = k * 256 + tid;
        if (it < 3600) {
            int oc = it & 15, tile = it >> 4;
            int ty = tile / 15, tx = tile - ty * 15;
            const float* mp = Mb + (size_t)tile * 4096 + oc;
            float Mv[16];
#pragma unroll
            for (int pos = 0; pos < 16; pos++) Mv[pos] = mp[pos * 256];
            float t0[4], t1[4];
#pragma unroll
            for (int j = 0; j < 4; j++) {
                t0[j] = Mv[j] + Mv[4 + j] + Mv[8 + j];
                t1[j] = Mv[4 + j] - Mv[8 + j] - Mv[12 + j];
            }
            float bs = xbias[oc];
            float* so = sxf + oc * SXSTR + (2 * ty) * 30 + 2 * tx;
            so[0]  = t0[0] + t0[1] + t0[2] + bs;
            so[1]  = t0[1] - t0[2] - t0[3] + bs;
            so[30] = t1[0] + t1[1] + t1[2] + bs;
            so[31] = t1[1] - t1[2] - t1[3] + bs;
        }
    }
    __syncthreads();

    // Phase 2: 16 oc x 625 outputs
    float* ob = out + (size_t)b * OSZ + ((size_t)img * 256 + ocb) * 625;
#pragma unroll 4
    for (int k = 0; k < 40; k++) {
        int it = k * 256 + tid;
        if (it < 10000) {
            int oc = it / 625, pix = it - oc * 625;
            int oy = pix / 25, ox = pix - oy * 25;
            const float* xp = sxf + oc * SXSTR + oy * 30 + ox;
            const float* zp = sz + oc * 36;
            float s = 0.f;
#pragma unroll
            for (int u = 0; u < 6; u++)
#pragma unroll
                for (int v = 0; v < 6; v++)
                    s = fmaf(zp[u * 6 + v], xp[u * 30 + v], s);
            ob[(size_t)oc * 625 + pix] = s;
        }
    }
}

// ============================ launch =========================================
extern "C" void kernel_launch(void* const* d_in, const int* in_sizes, int n_in,
                              void* d_out, int out_size) {
    const float* z = (const float*)d_in[0];
    const float* x = (const float*)d_in[1];

    PrepArgs pa;
    for (int p = 0; p < 4; p++) {
        pa.w[p] = (const float*)d_in[2 + p * 5 + 0];
        pa.g[p] = (const float*)d_in[2 + p * 5 + 1];
        pa.b[p] = (const float*)d_in[2 + p * 5 + 2];
        pa.m[p] = (const float*)d_in[2 + p * 5 + 3];
        pa.v[p] = (const float*)d_in[2 + p * 5 + 4];
    }

    cudaFuncSetAttribute(wino_gemm,
                         cudaFuncAttributeMaxDynamicSharedMemorySize, GEMM_SMEM);
    cudaFuncSetAttribute(wino_gemm,
                         cudaFuncAttributePreferredSharedMemoryCarveout, 100);
    cudaFuncSetAttribute(prep_xform,
                         cudaFuncAttributeMaxDynamicSharedMemorySize, XF_SMEM);
    cudaFuncSetAttribute(inv_xcorr,
                         cudaFuncAttributeMaxDynamicSharedMemorySize, IX_SMEM);

    prep_xform<<<2944, 256, XF_SMEM>>>(x, pa);
    xform_z<<<dim3(32, 32), 128>>>(z);
    wino_gemm<<<3840, 128, GEMM_SMEM>>>();
    inv_xcorr<<<dim3(16, 32, 2), 256, IX_SMEM>>>((float*)d_out);
}

// round 15
// speedup vs baseline: 1.3072x; 1.0700x over previous
#include <cuda_runtime.h>
#include <cuda_fp16.h>
#include <cstdint>

#define CIN 256
#define COUT 256
#define NB 32
#define OSZ (NB * COUT * 625)

// Winograd tile counts: x: 15x15*32 = 7200 (pad 7296 = 228*32), z: 288 (pad 384)
#define NTX 7296
#define NTZ 384
#define VSX ((size_t)NTX * 256)
#define VSZ ((size_t)NTZ * 256)

__device__ __align__(16) __half g_wU[4][16 * 256 * 512]; // [path][(pos*256+oc)*512 + comp*256+cin] hi/lo
__device__ float g_bias[4][COUT];
__device__ __align__(16) __half g_V[16 * NTX * 256];     // [pos][tile][cin] single fp16
__device__ __align__(16) __half g_Vz[16 * NTZ * 256];
__device__ float g_M[2][(size_t)NTX * 16 * 256];         // [branch][tile][pos][oc]
__device__ float g_Mz[2][(size_t)NTZ * 16 * 256];

struct PrepArgs {
    const float* w[4];
    const float* g[4];
    const float* b[4];
    const float* m[4];
    const float* v[4];
};

// ============================ helpers ========================================
__device__ __forceinline__ uint32_t smem_u32(const void* p) {
    uint32_t a;
    asm("{ .reg .u64 t; cvta.to.shared.u64 t, %1; cvt.u32.u64 %0, t; }"
        : "=r"(a) : "l"(p));
    return a;
}
__device__ __forceinline__ void cp16(uint32_t dst, const void* src) {
    asm volatile("cp.async.cg.shared.global [%0], [%1], 16;" :: "r"(dst), "l"(src));
}
__device__ __forceinline__ void cp_commit() {
    asm volatile("cp.async.commit_group;" ::: "memory");
}
template <int N>
__device__ __forceinline__ void cp_wait() {
    asm volatile("cp.async.wait_group %0;" :: "n"(N) : "memory");
}

#define LDSM4(r, addr)                                                         \
    asm volatile("ldmatrix.sync.aligned.m8n8.x4.shared.b16 {%0,%1,%2,%3},[%4];"\
        : "=r"((r)[0]), "=r"((r)[1]), "=r"((r)[2]), "=r"((r)[3]) : "r"(addr))

#define MMA(d, a, b0, b1)                                                      \
    asm volatile("mma.sync.aligned.m16n8k16.row.col.f32.f16.f16.f32 "          \
        "{%0,%1,%2,%3}, {%4,%5,%6,%7}, {%8,%9}, {%0,%1,%2,%3};"                \
        : "+f"((d)[0]), "+f"((d)[1]), "+f"((d)[2]), "+f"((d)[3])               \
        : "r"((a)[0]), "r"((a)[1]), "r"((a)[2]), "r"((a)[3]),                  \
          "r"(b0), "r"(b1))

__device__ __forceinline__ void hsplit(float v, __half& hi, __half& lo) {
    hi = __float2half_rn(v);
    lo = __float2half_rn(v - __half2float(hi));
}

__device__ __forceinline__ void wino_fwd(const float d[4][4], float V[4][4]) {
    float t[4][4];
#pragma unroll
    for (int j = 0; j < 4; j++) {
        t[0][j] = d[0][j] - d[2][j];
        t[1][j] = d[1][j] + d[2][j];
        t[2][j] = d[2][j] - d[1][j];
        t[3][j] = d[1][j] - d[3][j];
    }
#pragma unroll
    for (int i = 0; i < 4; i++) {
        V[i][0] = t[i][0] - t[i][2];
        V[i][1] = t[i][1] + t[i][2];
        V[i][2] = t[i][2] - t[i][1];
        V[i][3] = t[i][1] - t[i][3];
    }
}

// =============== fused: weight transform (prep) + x input transform ==========
// blocks 0..1919: xform_x; blocks 1920..2943: prep
#define SDSTR 129
#define XF_SD_BYTES (64 * SDSTR * 4)                 // 33024
#define XF_SMEM (XF_SD_BYTES + 15 * 16 * 64 * 2)     // 63744

__global__ __launch_bounds__(256)
void prep_xform(const float* __restrict__ x, PrepArgs a) {
    const int tid = threadIdx.x;
    if (blockIdx.x >= 1920) {
        int i = (blockIdx.x - 1920) * 256 + tid;     // 262144 items
        int path = i >> 16;
        int oc   = (i >> 8) & 255;
        int cin  = i & 255;
        float inv = a.g[path][oc] * rsqrtf(a.v[path][oc] + 1e-5f);
        const float* wp = a.w[path] + oc * 2304 + cin * 9;
        float w[3][3];
#pragma unroll
        for (int r = 0; r < 3; r++)
#pragma unroll
            for (int c = 0; c < 3; c++) w[r][c] = wp[r * 3 + c] * inv;
        float T[4][3];
#pragma unroll
        for (int j = 0; j < 3; j++) {
            T[0][j] = w[0][j];
            T[1][j] = 0.5f * (w[0][j] + w[1][j] + w[2][j]);
            T[2][j] = 0.5f * (w[0][j] - w[1][j] + w[2][j]);
            T[3][j] = w[2][j];
        }
#pragma unroll
        for (int r = 0; r < 4; r++) {
            float U[4];
            U[0] = T[r][0];
            U[1] = 0.5f * (T[r][0] + T[r][1] + T[r][2]);
            U[2] = 0.5f * (T[r][0] - T[r][1] + T[r][2]);
            U[3] = T[r][2];
#pragma unroll
            for (int c = 0; c < 4; c++) {
                __half hi, lo;
                hsplit(U[c], hi, lo);
                size_t base = ((size_t)((r * 4 + c) * 256 + oc)) * 512 + cin;
                g_wU[path][base]       = hi;
                g_wU[path][base + 256] = lo;
            }
        }
        if (i < 1024) {
            int p2 = i >> 8, oc2 = i & 255;
            float inv2 = a.g[p2][oc2] * rsqrtf(a.v[p2][oc2] + 1e-5f);
            g_bias[p2][oc2] = a.b[p2][oc2] - a.m[p2][oc2] * inv2;
        }
        return;
    }

    extern __shared__ __align__(16) char xsm[];
    float* sd = (float*)xsm;
    __half* sV = (__half*)(xsm + XF_SD_BYTES);       // [tile][pos][64]
    const int bid = blockIdx.x;
    const int ty  = bid >> 7;
    const int cg  = (bid >> 5) & 3;
    const int img = bid & 31;
    const int c0 = cg * 64;
    const float* src = x + ((size_t)img * 256 + c0) * 1024 + 2 * ty * 32;

#pragma unroll
    for (int k = 0; k < 32; k++) {
        int id = k * 256 + tid;
        int c = id >> 7, rc = id & 127;
        sd[c * SDSTR + rc] = src[(size_t)c * 1024 + rc];
    }
    __syncthreads();

#pragma unroll
    for (int k = 0; k < 4; k++) {
        int id = k * 256 + tid;
        if (id < 960) {
            int tx = id >> 6, c = id & 63;
            const float* p = sd + c * SDSTR + 2 * tx;
            float d[4][4], V[4][4];
#pragma unroll
            for (int i = 0; i < 4; i++)
#pragma unroll
                for (int j = 0; j < 4; j++) d[i][j] = p[i * 32 + j];
            wino_fwd(d, V);
#pragma unroll
            for (int i = 0; i < 4; i++)
#pragma unroll
                for (int j = 0; j < 4; j++)
                    sV[(tx * 16 + (i * 4 + j)) * 64 + c] = __float2half_rn(V[i][j]);
        }
    }
    __syncthreads();

#pragma unroll
    for (int k = 0; k < 8; k++) {                    // 1920 uint4
        int id = k * 256 + tid;
        if (id < 1920) {
            int q    = id & 7;
            int pos  = (id >> 3) & 15;
            int tile = id >> 7;
            uint4 v = *(const uint4*)(sV + (tile * 16 + pos) * 64 + q * 8);
            *(uint4*)(g_V + (size_t)pos * VSX +
                      ((size_t)img * 225 + ty * 15 + tile) * 256 + c0 + q * 8) = v;
        }
    }
}

__global__ __launch_bounds__(128)
void xform_z(const float* __restrict__ z) {
    __shared__ float sd[8][64];
    __shared__ __align__(16) __half sVz[9][16][8];
    const int img = blockIdx.x, cg = blockIdx.y, tid = threadIdx.x;
    const float* src = z + ((size_t)img * 256 + cg * 8) * 64;
#pragma unroll
    for (int k = 0; k < 4; k++) {
        int lin = k * 128 + tid;
        sd[lin >> 6][lin & 63] = src[lin];
    }
    __syncthreads();
    if (tid < 72) {
        int tl = tid >> 3, c = tid & 7;
        int ty = tl / 3, tx = tl - ty * 3;
        float d[4][4], V[4][4];
#pragma unroll
        for (int i = 0; i < 4; i++)
#pragma unroll
            for (int j = 0; j < 4; j++)
                d[i][j] = sd[c][(2 * ty + i) * 8 + 2 * tx + j];
        wino_fwd(d, V);
#pragma unroll
        for (int i = 0; i < 4; i++)
#pragma unroll
            for (int j = 0; j < 4; j++)
                sVz[tl][i * 4 + j][c] = __float2half_rn(V[i][j]);
    }
    __syncthreads();
#pragma unroll
    for (int k = 0; k < 2; k++) {
        int cid = k * 128 + tid;                     // 144 uint4
        if (cid < 144) {
            int pos = cid & 15, tl = cid >> 4;
            uint4 val = *(const uint4*)&sVz[tl][pos][0];
            *(uint4*)(g_Vz + (size_t)pos * VSZ +
                      ((size_t)img * 9 + tl) * 256 + cg * 8) = val;
        }
    }
}

// ============================ batched GEMM ===================================
// D[128 tile, 128 oc] = V[128,256] * U[128,256]^T.
// A (V) single fp16; B (U) hi+lo fp16 split. K-chunk 64, 4 warps, 2 CTAs/SM.
#define ASTR 144u
#define ABUF (128u * ASTR)         // 18432
#define BSTR 272u
#define BBUF (128u * BSTR)         // 34816
#define BOFF (2u * ABUF)           // 36864
#define GEMM_SMEM (BOFF + 2u * BBUF)   // 106496

__global__ __launch_bounds__(128, 2)
void wino_gemm() {
    extern __shared__ __align__(16) char smem[];
    const int tid = threadIdx.x, lid = tid & 31, wid = tid >> 5;
    const int warp_m = wid >> 1, warp_n = wid & 1;
    const uint32_t sBu = smem_u32(smem);

    const int bid = blockIdx.x;
    const __half *vsrc, *wsrc;
    float* mdst;
    if (bid < 3648) {
        int combo = bid & 3, b = combo >> 1, o = combo & 1;
        int group = bid >> 2;
        int p = group / 57, mt = group - p * 57;
        vsrc = g_V + (size_t)p * VSX + (size_t)mt * 128 * 256;
        wsrc = g_wU[1 + 2 * b] + ((size_t)(p * 256) + o * 128) * 512;
        mdst = g_M[b] + ((size_t)mt * 128) * 4096 + p * 256 + o * 128;
    } else {
        int zb = bid - 3648;
        int combo = zb & 3, b = combo >> 1, o = combo & 1;
        int group = zb >> 2;
        int p = group / 3, mt = group - p * 3;
        vsrc = g_Vz + (size_t)p * VSZ + (size_t)mt * 128 * 256;
        wsrc = g_wU[2 * b] + ((size_t)(p * 256) + o * 128) * 512;
        mdst = g_Mz[b] + ((size_t)mt * 128) * 4096 + p * 256 + o * 128;
    }

    float acc[4][8][4];
#pragma unroll
    for (int t = 0; t < 4; t++)
#pragma unroll
        for (int j = 0; j < 8; j++)
#pragma unroll
            for (int e = 0; e < 4; e++) acc[t][j][e] = 0.f;

    auto copyAB = [&](int g) {
        const int buf = g & 1, c0 = g * 64;
#pragma unroll
        for (int k = 0; k < 8; k++) {                // A: 1024 cp16
            int id = tid + k * 128;
            int row = id >> 3, kq = id & 7;
            cp16(sBu + buf * ABUF + row * ASTR + kq * 16,
                 vsrc + (size_t)row * 256 + c0 + kq * 8);
        }
#pragma unroll
        for (int k = 0; k < 16; k++) {               // B: 2048 cp16 (hi+lo)
            int id = tid + k * 128;
            int row = id >> 4, part = id & 15, comp = part >> 3, kq = part & 7;
            cp16(sBu + BOFF + buf * BBUF + row * BSTR + comp * 128 + kq * 16,
                 wsrc + (size_t)row * 512 + comp * 256 + c0 + kq * 8);
        }
        cp_commit();
    };

    copyAB(0);
#pragma unroll 1
    for (int g = 0; g < 4; g++) {
        const int buf = g & 1;
        cp_wait<0>();
        __syncthreads();
        if (g + 1 < 4) copyAB(g + 1);

        uint32_t aaddr[4], baddr[4];
#pragma unroll
        for (int t = 0; t < 4; t++) {
            int m = warp_m * 64 + t * 16 + (lid & 7) + ((lid >> 3) & 1) * 8;
            aaddr[t] = sBu + buf * ABUF + m * ASTR + ((lid >> 4) << 4);
        }
#pragma unroll
        for (int j = 0; j < 4; j++) {
            int n = warp_n * 64 + j * 16 + (lid & 7) + (lid >> 4) * 8;
            baddr[j] = sBu + BOFF + buf * BBUF + n * BSTR + (((lid >> 3) & 1) << 4);
        }

#pragma unroll
        for (int ks = 0; ks < 4; ks++) {
            uint32_t ah[4][4], bh[4][4], bl[4][4];
#pragma unroll
            for (int t = 0; t < 4; t++) LDSM4(ah[t], aaddr[t] + ks * 32);
#pragma unroll
            for (int j = 0; j < 4; j++) LDSM4(bh[j], baddr[j] + ks * 32);
#pragma unroll
            for (int j = 0; j < 4; j++) LDSM4(bl[j], baddr[j] + ks * 32 + 128);
#pragma unroll
            for (int t = 0; t < 4; t++)
#pragma unroll
                for (int j = 0; j < 4; j++) {
                    MMA(acc[t][2 * j],     ah[t], bh[j][0], bh[j][1]);
                    MMA(acc[t][2 * j + 1], ah[t], bh[j][2], bh[j][3]);
                }
#pragma unroll
            for (int t = 0; t < 4; t++)
#pragma unroll
                for (int j = 0; j < 4; j++) {
                    MMA(acc[t][2 * j],     ah[t], bl[j][0], bl[j][1]);
                    MMA(acc[t][2 * j + 1], ah[t], bl[j][2], bl[j][3]);
                }
        }
    }

    // epilogue: [tile][pos][oc] stores; tile stride 4096 floats
#pragma unroll
    for (int t = 0; t < 4; t++) {
        int r = warp_m * 64 + t * 16 + (lid >> 2);
#pragma unroll
        for (int jj = 0; jj < 8; jj++) {
            int c = warp_n * 64 + (jj >> 1) * 16 + (jj & 1) * 8 + (lid & 3) * 2;
            float* base = mdst + (size_t)r * 4096 + c;
            *(float2*)base = make_float2(acc[t][jj][0], acc[t][jj][1]);
            *(float2*)(base + (size_t)8 * 4096) = make_float2(acc[t][jj][2], acc[t][jj][3]);
        }
    }
}

// ====== fused: z inverse transform + x inverse transform + depthwise xcorr ===
#define SXSTR 901
#define IX_SXF_BYTES (16 * SXSTR * 4)               // 57664
#define IX_SMEM (IX_SXF_BYTES + 16 * 36 * 4)        // 59968

__global__ __launch_bounds__(256)
void inv_xcorr(float* __restrict__ out) {
    extern __shared__ __align__(16) char ism[];
    float* sxf = (float*)ism;                        // [16][SXSTR]
    float* sz  = (float*)(ism + IX_SXF_BYTES);       // [16][36]

    const int ocq = blockIdx.x, img = blockIdx.y, b = blockIdx.z;
    const int tid = threadIdx.x;
    const int ocb = ocq * 16;

    // z slab: 16 oc x 9 tiles = 144 items
    if (tid < 144) {
        int oc = tid & 15, t = tid >> 4;
        int ty = t / 3, tx = t - ty * 3;
        const float* mp = g_Mz[b] + ((size_t)(img * 9 + t)) * 4096 + ocb + oc;
        float Mv[16];
#pragma unroll
        for (int pos = 0; pos < 16; pos++) Mv[pos] = mp[pos * 256];
        float t0[4], t1[4];
#pragma unroll
        for (int j = 0; j < 4; j++) {
            t0[j] = Mv[j] + Mv[4 + j] + Mv[8 + j];
            t1[j] = Mv[4 + j] - Mv[8 + j] - Mv[12 + j];
        }
        float bz = g_bias[2 * b][ocb + oc];
        float* so = sz + oc * 36 + (2 * ty) * 6 + 2 * tx;
        so[0] = t0[0] + t0[1] + t0[2] + bz;
        so[1] = t0[1] - t0[2] - t0[3] + bz;
        so[6] = t1[0] + t1[1] + t1[2] + bz;
        so[7] = t1[1] - t1[2] - t1[3] + bz;
    }

    // Phase 1: 225 tiles x 16 oc = 3600 items
    const float* Mb = g_M[b] + (size_t)img * 225 * 4096 + ocb;
    const float* xbias = g_bias[1 + 2 * b] + ocb;
#pragma unroll
    for (int k = 0; k < 15; k++) {
        int it = k * 256 + tid;
        if (it < 3600) {
            int oc = it & 15, tile = it >> 4;
            int ty = tile / 15, tx = tile - ty * 15;
            const float* mp = Mb + (size_t)tile * 4096 + oc;
            float Mv[16];
#pragma unroll
            for (int pos = 0; pos < 16; pos++) Mv[pos] = mp[pos * 256];
            float t0[4], t1[4];
#pragma unroll
            for (int j = 0; j < 4; j++) {
                t0[j] = Mv[j] + Mv[4 + j] + Mv[8 + j];
                t1[j] = Mv[4 + j] - Mv[8 + j] - Mv[12 + j];
            }
            float bs = xbias[oc];
            float* so = sxf + oc * SXSTR + (2 * ty) * 30 + 2 * tx;
            so[0]  = t0[0] + t0[1] + t0[2] + bs;
            so[1]  = t0[1] - t0[2] - t0[3] + bs;
            so[30] = t1[0] + t1[1] + t1[2] + bs;
            so[31] = t1[1] - t1[2] - t1[3] + bs;
        }
    }
    __syncthreads();

    // Phase 2: warp-per-oc — z taps hoisted to registers, x loads lane-parallel
    const int warp = tid >> 5, lane = tid & 31;
    float* ob = out + (size_t)b * OSZ + ((size_t)img * 256 + ocb) * 625;
#pragma unroll
    for (int s = 0; s < 2; s++) {
        const int oc = warp * 2 + s;                 // 8 warps x 2 = 16 oc
        float zr[36];
        const float* zp = sz + oc * 36;
#pragma unroll
        for (int i = 0; i < 36; i++) zr[i] = zp[i];  // broadcast LDS
        const float* xp0 = sxf + oc * SXSTR;
        float* op = ob + (size_t)oc * 625;
#pragma unroll 2
        for (int it = 0; it < 20; it++) {
            int pix = it * 32 + lane;
            if (pix < 625) {
                int oy = pix / 25, ox = pix - oy * 25;
                const float* xp = xp0 + oy * 30 + ox;
                float acc = 0.f;
#pragma unroll
                for (int u = 0; u < 6; u++)
#pragma unroll
                    for (int v = 0; v < 6; v++)
                        acc = fmaf(zr[u * 6 + v], xp[u * 30 + v], acc);
                op[pix] = acc;
            }
        }
    }
}

// ============================ launch =========================================
extern "C" void kernel_launch(void* const* d_in, const int* in_sizes, int n_in,
                              void* d_out, int out_size) {
    const float* z = (const float*)d_in[0];
    const float* x = (const float*)d_in[1];

    PrepArgs pa;
    for (int p = 0; p < 4; p++) {
        pa.w[p] = (const float*)d_in[2 + p * 5 + 0];
        pa.g[p] = (const float*)d_in[2 + p * 5 + 1];
        pa.b[p] = (const float*)d_in[2 + p * 5 + 2];
        pa.m[p] = (const float*)d_in[2 + p * 5 + 3];
        pa.v[p] = (const float*)d_in[2 + p * 5 + 4];
    }

    cudaFuncSetAttribute(wino_gemm,
                         cudaFuncAttributeMaxDynamicSharedMemorySize, GEMM_SMEM);
    cudaFuncSetAttribute(wino_gemm,
                         cudaFuncAttributePreferredSharedMemoryCarveout, 100);
    cudaFuncSetAttribute(prep_xform,
                         cudaFuncAttributeMaxDynamicSharedMemorySize, XF_SMEM);
    cudaFuncSetAttribute(inv_xcorr,
                         cudaFuncAttributeMaxDynamicSharedMemorySize, IX_SMEM);

    prep_xform<<<2944, 256, XF_SMEM>>>(x, pa);
    xform_z<<<dim3(32, 32), 128>>>(z);
    wino_gemm<<<3840, 128, GEMM_SMEM>>>();
    inv_xcorr<<<dim3(16, 32, 2), 256, IX_SMEM>>>((float*)d_out);
}

// round 16
// speedup vs baseline: 1.4118x; 1.0800x over previous
#include <cuda_runtime.h>
#include <cuda_fp16.h>
#include <cstdint>

#define CIN 256
#define COUT 256
#define NB 32
#define OSZ (NB * COUT * 625)

// Winograd tile counts: x: 15x15*32 = 7200 (pad 7296 = 228*32), z: 288 (pad 384)
#define NTX 7296
#define NTZ 384
#define VSX ((size_t)NTX * 256)
#define VSZ ((size_t)NTZ * 256)

__device__ __align__(16) __half g_wU[4][16 * 256 * 512]; // [path][(pos*256+oc)*512 + comp*256+cin] hi/lo
__device__ float g_bias[4][COUT];
__device__ __align__(16) __half g_V[16 * NTX * 256];     // [pos][tile][cin] single fp16
__device__ __align__(16) __half g_Vz[16 * NTZ * 256];
__device__ float g_M[2][(size_t)NTX * 16 * 256];         // [branch][tile][pos][oc]
__device__ float g_Mz[2][(size_t)NTZ * 16 * 256];

struct PrepArgs {
    const float* w[4];
    const float* g[4];
    const float* b[4];
    const float* m[4];
    const float* v[4];
};

// ============================ helpers ========================================
__device__ __forceinline__ uint32_t smem_u32(const void* p) {
    uint32_t a;
    asm("{ .reg .u64 t; cvta.to.shared.u64 t, %1; cvt.u32.u64 %0, t; }"
        : "=r"(a) : "l"(p));
    return a;
}
__device__ __forceinline__ void cp16(uint32_t dst, const void* src) {
    asm volatile("cp.async.cg.shared.global [%0], [%1], 16;" :: "r"(dst), "l"(src));
}
__device__ __forceinline__ void cp_commit() {
    asm volatile("cp.async.commit_group;" ::: "memory");
}
template <int N>
__device__ __forceinline__ void cp_wait() {
    asm volatile("cp.async.wait_group %0;" :: "n"(N) : "memory");
}

#define LDSM4(r, addr)                                                         \
    asm volatile("ldmatrix.sync.aligned.m8n8.x4.shared.b16 {%0,%1,%2,%3},[%4];"\
        : "=r"((r)[0]), "=r"((r)[1]), "=r"((r)[2]), "=r"((r)[3]) : "r"(addr))

#define MMA(d, a, b0, b1)                                                      \
    asm volatile("mma.sync.aligned.m16n8k16.row.col.f32.f16.f16.f32 "          \
        "{%0,%1,%2,%3}, {%4,%5,%6,%7}, {%8,%9}, {%0,%1,%2,%3};"                \
        : "+f"((d)[0]), "+f"((d)[1]), "+f"((d)[2]), "+f"((d)[3])               \
        : "r"((a)[0]), "r"((a)[1]), "r"((a)[2]), "r"((a)[3]),                  \
          "r"(b0), "r"(b1))

__device__ __forceinline__ void hsplit(float v, __half& hi, __half& lo) {
    hi = __float2half_rn(v);
    lo = __float2half_rn(v - __half2float(hi));
}

__device__ __forceinline__ void wino_fwd(const float d[4][4], float V[4][4]) {
    float t[4][4];
#pragma unroll
    for (int j = 0; j < 4; j++) {
        t[0][j] = d[0][j] - d[2][j];
        t[1][j] = d[1][j] + d[2][j];
        t[2][j] = d[2][j] - d[1][j];
        t[3][j] = d[1][j] - d[3][j];
    }
#pragma unroll
    for (int i = 0; i < 4; i++) {
        V[i][0] = t[i][0] - t[i][2];
        V[i][1] = t[i][1] + t[i][2];
        V[i][2] = t[i][2] - t[i][1];
        V[i][3] = t[i][1] - t[i][3];
    }
}

// =============== fused: weight transform (prep) + x input transform ==========
// blocks 0..1919: xform_x; blocks 1920..2943: prep
#define SDSTR 129
#define XF_SD_BYTES (64 * SDSTR * 4)                 // 33024
#define XF_SMEM (XF_SD_BYTES + 15 * 16 * 64 * 2)     // 63744

__global__ __launch_bounds__(256)
void prep_xform(const float* __restrict__ x, PrepArgs a) {
    const int tid = threadIdx.x;
    if (blockIdx.x >= 1920) {
        int i = (blockIdx.x - 1920) * 256 + tid;     // 262144 items
        int path = i >> 16;
        int oc   = (i >> 8) & 255;
        int cin  = i & 255;
        float inv = a.g[path][oc] * rsqrtf(a.v[path][oc] + 1e-5f);
        const float* wp = a.w[path] + oc * 2304 + cin * 9;
        float w[3][3];
#pragma unroll
        for (int r = 0; r < 3; r++)
#pragma unroll
            for (int c = 0; c < 3; c++) w[r][c] = wp[r * 3 + c] * inv;
        float T[4][3];
#pragma unroll
        for (int j = 0; j < 3; j++) {
            T[0][j] = w[0][j];
            T[1][j] = 0.5f * (w[0][j] + w[1][j] + w[2][j]);
            T[2][j] = 0.5f * (w[0][j] - w[1][j] + w[2][j]);
            T[3][j] = w[2][j];
        }
#pragma unroll
        for (int r = 0; r < 4; r++) {
            float U[4];
            U[0] = T[r][0];
            U[1] = 0.5f * (T[r][0] + T[r][1] + T[r][2]);
            U[2] = 0.5f * (T[r][0] - T[r][1] + T[r][2]);
            U[3] = T[r][2];
#pragma unroll
            for (int c = 0; c < 4; c++) {
                __half hi, lo;
                hsplit(U[c], hi, lo);
                size_t base = ((size_t)((r * 4 + c) * 256 + oc)) * 512 + cin;
                g_wU[path][base]       = hi;
                g_wU[path][base + 256] = lo;
            }
        }
        if (i < 1024) {
            int p2 = i >> 8, oc2 = i & 255;
            float inv2 = a.g[p2][oc2] * rsqrtf(a.v[p2][oc2] + 1e-5f);
            g_bias[p2][oc2] = a.b[p2][oc2] - a.m[p2][oc2] * inv2;
        }
        return;
    }

    extern __shared__ __align__(16) char xsm[];
    float* sd = (float*)xsm;
    __half* sV = (__half*)(xsm + XF_SD_BYTES);       // [tile][pos][64]
    const int bid = blockIdx.x;
    const int ty  = bid >> 7;
    const int cg  = (bid >> 5) & 3;
    const int img = bid & 31;
    const int c0 = cg * 64;
    const float* src = x + ((size_t)img * 256 + c0) * 1024 + 2 * ty * 32;

#pragma unroll
    for (int k = 0; k < 32; k++) {
        int id = k * 256 + tid;
        int c = id >> 7, rc = id & 127;
        sd[c * SDSTR + rc] = src[(size_t)c * 1024 + rc];
    }
    __syncthreads();

#pragma unroll
    for (int k = 0; k < 4; k++) {
        int id = k * 256 + tid;
        if (id < 960) {
            int tx = id >> 6, c = id & 63;
            const float* p = sd + c * SDSTR + 2 * tx;
            float d[4][4], V[4][4];
#pragma unroll
            for (int i = 0; i < 4; i++)
#pragma unroll
                for (int j = 0; j < 4; j++) d[i][j] = p[i * 32 + j];
            wino_fwd(d, V);
#pragma unroll
            for (int i = 0; i < 4; i++)
#pragma unroll
                for (int j = 0; j < 4; j++)
                    sV[(tx * 16 + (i * 4 + j)) * 64 + c] = __float2half_rn(V[i][j]);
        }
    }
    __syncthreads();

#pragma unroll
    for (int k = 0; k < 8; k++) {                    // 1920 uint4
        int id = k * 256 + tid;
        if (id < 1920) {
            int q    = id & 7;
            int pos  = (id >> 3) & 15;
            int tile = id >> 7;
            uint4 v = *(const uint4*)(sV + (tile * 16 + pos) * 64 + q * 8);
            *(uint4*)(g_V + (size_t)pos * VSX +
                      ((size_t)img * 225 + ty * 15 + tile) * 256 + c0 + q * 8) = v;
        }
    }
}

__global__ __launch_bounds__(128)
void xform_z(const float* __restrict__ z) {
    __shared__ float sd[8][64];
    __shared__ __align__(16) __half sVz[9][16][8];
    const int img = blockIdx.x, cg = blockIdx.y, tid = threadIdx.x;
    const float* src = z + ((size_t)img * 256 + cg * 8) * 64;
#pragma unroll
    for (int k = 0; k < 4; k++) {
        int lin = k * 128 + tid;
        sd[lin >> 6][lin & 63] = src[lin];
    }
    __syncthreads();
    if (tid < 72) {
        int tl = tid >> 3, c = tid & 7;
        int ty = tl / 3, tx = tl - ty * 3;
        float d[4][4], V[4][4];
#pragma unroll
        for (int i = 0; i < 4; i++)
#pragma unroll
            for (int j = 0; j < 4; j++)
                d[i][j] = sd[c][(2 * ty + i) * 8 + 2 * tx + j];
        wino_fwd(d, V);
#pragma unroll
        for (int i = 0; i < 4; i++)
#pragma unroll
            for (int j = 0; j < 4; j++)
                sVz[tl][i * 4 + j][c] = __float2half_rn(V[i][j]);
    }
    __syncthreads();
#pragma unroll
    for (int k = 0; k < 2; k++) {
        int cid = k * 128 + tid;                     // 144 uint4
        if (cid < 144) {
            int pos = cid & 15, tl = cid >> 4;
            uint4 val = *(const uint4*)&sVz[tl][pos][0];
            *(uint4*)(g_Vz + (size_t)pos * VSZ +
                      ((size_t)img * 9 + tl) * 256 + cg * 8) = val;
        }
    }
}

// ============================ batched GEMM ===================================
// D[128 tile, 128 oc] = V[128,256] * U[128,256]^T.
// A (V) single fp16; B (U) hi+lo fp16 split. K-chunk 64, 4 warps, 2 CTAs/SM.
#define ASTR 144u
#define ABUF (128u * ASTR)         // 18432
#define BSTR 272u
#define BBUF (128u * BSTR)         // 34816
#define BOFF (2u * ABUF)           // 36864
#define GEMM_SMEM (BOFF + 2u * BBUF)   // 106496

__global__ __launch_bounds__(128, 2)
void wino_gemm() {
    extern __shared__ __align__(16) char smem[];
    const int tid = threadIdx.x, lid = tid & 31, wid = tid >> 5;
    const int warp_m = wid >> 1, warp_n = wid & 1;
    const uint32_t sBu = smem_u32(smem);

    const int bid = blockIdx.x;
    const __half *vsrc, *wsrc;
    float* mdst;
    if (bid < 3648) {
        int combo = bid & 3, b = combo >> 1, o = combo & 1;
        int group = bid >> 2;
        int p = group / 57, mt = group - p * 57;
        vsrc = g_V + (size_t)p * VSX + (size_t)mt * 128 * 256;
        wsrc = g_wU[1 + 2 * b] + ((size_t)(p * 256) + o * 128) * 512;
        mdst = g_M[b] + ((size_t)mt * 128) * 4096 + p * 256 + o * 128;
    } else {
        int zb = bid - 3648;
        int combo = zb & 3, b = combo >> 1, o = combo & 1;
        int group = zb >> 2;
        int p = group / 3, mt = group - p * 3;
        vsrc = g_Vz + (size_t)p * VSZ + (size_t)mt * 128 * 256;
        wsrc = g_wU[2 * b] + ((size_t)(p * 256) + o * 128) * 512;
        mdst = g_Mz[b] + ((size_t)mt * 128) * 4096 + p * 256 + o * 128;
    }

    float acc[4][8][4];
#pragma unroll
    for (int t = 0; t < 4; t++)
#pragma unroll
        for (int j = 0; j < 8; j++)
#pragma unroll
            for (int e = 0; e < 4; e++) acc[t][j][e] = 0.f;

    auto copyAB = [&](int g) {
        const int buf = g & 1, c0 = g * 64;
#pragma unroll
        for (int k = 0; k < 8; k++) {                // A: 1024 cp16
            int id = tid + k * 128;
            int row = id >> 3, kq = id & 7;
            cp16(sBu + buf * ABUF + row * ASTR + kq * 16,
                 vsrc + (size_t)row * 256 + c0 + kq * 8);
        }
#pragma unroll
        for (int k = 0; k < 16; k++) {               // B: 2048 cp16 (hi+lo)
            int id = tid + k * 128;
            int row = id >> 4, part = id & 15, comp = part >> 3, kq = part & 7;
            cp16(sBu + BOFF + buf * BBUF + row * BSTR + comp * 128 + kq * 16,
                 wsrc + (size_t)row * 512 + comp * 256 + c0 + kq * 8);
        }
        cp_commit();
    };

    copyAB(0);
#pragma unroll 1
    for (int g = 0; g < 4; g++) {
        const int buf = g & 1;
        cp_wait<0>();
        __syncthreads();
        if (g + 1 < 4) copyAB(g + 1);

        uint32_t aaddr[4], baddr[4];
#pragma unroll
        for (int t = 0; t < 4; t++) {
            int m = warp_m * 64 + t * 16 + (lid & 7) + ((lid >> 3) & 1) * 8;
            aaddr[t] = sBu + buf * ABUF + m * ASTR + ((lid >> 4) << 4);
        }
#pragma unroll
        for (int j = 0; j < 4; j++) {
            int n = warp_n * 64 + j * 16 + (lid & 7) + (lid >> 4) * 8;
            baddr[j] = sBu + BOFF + buf * BBUF + n * BSTR + (((lid >> 3) & 1) << 4);
        }

#pragma unroll
        for (int ks = 0; ks < 4; ks++) {
            uint32_t ah[4][4], bh[4][4], bl[4][4];
#pragma unroll
            for (int t = 0; t < 4; t++) LDSM4(ah[t], aaddr[t] + ks * 32);
#pragma unroll
            for (int j = 0; j < 4; j++) LDSM4(bh[j], baddr[j] + ks * 32);
#pragma unroll
            for (int j = 0; j < 4; j++) LDSM4(bl[j], baddr[j] + ks * 32 + 128);
#pragma unroll
            for (int t = 0; t < 4; t++)
#pragma unroll
                for (int j = 0; j < 4; j++) {
                    MMA(acc[t][2 * j],     ah[t], bh[j][0], bh[j][1]);
                    MMA(acc[t][2 * j + 1], ah[t], bh[j][2], bh[j][3]);
                }
#pragma unroll
            for (int t = 0; t < 4; t++)
#pragma unroll
                for (int j = 0; j < 4; j++) {
                    MMA(acc[t][2 * j],     ah[t], bl[j][0], bl[j][1]);
                    MMA(acc[t][2 * j + 1], ah[t], bl[j][2], bl[j][3]);
                }
        }
    }

    // epilogue: [tile][pos][oc] stores; tile stride 4096 floats
#pragma unroll
    for (int t = 0; t < 4; t++) {
        int r = warp_m * 64 + t * 16 + (lid >> 2);
#pragma unroll
        for (int jj = 0; jj < 8; jj++) {
            int c = warp_n * 64 + (jj >> 1) * 16 + (jj & 1) * 8 + (lid & 3) * 2;
            float* base = mdst + (size_t)r * 4096 + c;
            *(float2*)base = make_float2(acc[t][jj][0], acc[t][jj][1]);
            *(float2*)(base + (size_t)8 * 4096) = make_float2(acc[t][jj][2], acc[t][jj][3]);
        }
    }
}

// ====== fused: z inverse transform + x inverse transform + depthwise xcorr ===
#define SXSTR 901
#define IX_SXF_BYTES (16 * SXSTR * 4)               // 57664
#define IX_SMEM (IX_SXF_BYTES + 16 * 36 * 4)        // 59968

__global__ __launch_bounds__(256)
void inv_xcorr(float* __restrict__ out) {
    extern __shared__ __align__(16) char ism[];
    float* sxf = (float*)ism;                        // [16][SXSTR]
    float* sz  = (float*)(ism + IX_SXF_BYTES);       // [16][36]

    const int ocq = blockIdx.x, img = blockIdx.y, b = blockIdx.z;
    const int tid = threadIdx.x;
    const int ocb = ocq * 16;

    // z slab: 16 oc x 9 tiles = 144 items
    if (tid < 144) {
        int oc = tid & 15, t = tid >> 4;
        int ty = t / 3, tx = t - ty * 3;
        const float* mp = g_Mz[b] + ((size_t)(img * 9 + t)) * 4096 + ocb + oc;
        float Mv[16];
#pragma unroll
        for (int pos = 0; pos < 16; pos++) Mv[pos] = mp[pos * 256];
        float t0[4], t1[4];
#pragma unroll
        for (int j = 0; j < 4; j++) {
            t0[j] = Mv[j] + Mv[4 + j] + Mv[8 + j];
            t1[j] = Mv[4 + j] - Mv[8 + j] - Mv[12 + j];
        }
        float bz = g_bias[2 * b][ocb + oc];
        float* so = sz + oc * 36 + (2 * ty) * 6 + 2 * tx;
        so[0] = t0[0] + t0[1] + t0[2] + bz;
        so[1] = t0[1] - t0[2] - t0[3] + bz;
        so[6] = t1[0] + t1[1] + t1[2] + bz;
        so[7] = t1[1] - t1[2] - t1[3] + bz;
    }

    // Phase 1: 225 tiles x 16 oc = 3600 items
    const float* Mb = g_M[b] + (size_t)img * 225 * 4096 + ocb;
    const float* xbias = g_bias[1 + 2 * b] + ocb;
#pragma unroll
    for (int k = 0; k < 15; k++) {
        int it = k * 256 + tid;
        if (it < 3600) {
            int oc = it & 15, tile = it >> 4;
            int ty = tile / 15, tx = tile - ty * 15;
            const float* mp = Mb + (size_t)tile * 4096 + oc;
            float Mv[16];
#pragma unroll
            for (int pos = 0; pos < 16; pos++) Mv[pos] = mp[pos * 256];
            float t0[4], t1[4];
#pragma unroll
            for (int j = 0; j < 4; j++) {
                t0[j] = Mv[j] + Mv[4 + j] + Mv[8 + j];
                t1[j] = Mv[4 + j] - Mv[8 + j] - Mv[12 + j];
            }
            float bs = xbias[oc];
            float* so = sxf + oc * SXSTR + (2 * ty) * 30 + 2 * tx;
            so[0]  = t0[0] + t0[1] + t0[2] + bs;
            so[1]  = t0[1] - t0[2] - t0[3] + bs;
            so[30] = t1[0] + t1[1] + t1[2] + bs;
            so[31] = t1[1] - t1[2] - t1[3] + bs;
        }
    }
    __syncthreads();

    // Phase 2: row-sliding xcorr — lane owns output row; x row loaded once
    // into registers per (oc, u), all 25 columns computed from the window.
    const int warp = tid >> 5, lane = tid & 31;
    float* ob = out + (size_t)b * OSZ + ((size_t)img * 256 + ocb) * 625;
#pragma unroll
    for (int s = 0; s < 2; s++) {
        const int oc = warp * 2 + s;                 // 8 warps x 2 = 16 oc
        if (lane < 25) {
            const float* xp0 = sxf + oc * SXSTR + lane * 30;
            const float* zp  = sz + oc * 36;
            float acc[25];
#pragma unroll
            for (int i = 0; i < 25; i++) acc[i] = 0.f;
#pragma unroll
            for (int u = 0; u < 6; u++) {
                float xrow[30];
                const float* xr = xp0 + u * 30;
#pragma unroll
                for (int i = 0; i < 30; i++) xrow[i] = xr[i];
#pragma unroll
                for (int v = 0; v < 6; v++) {
                    float zv = zp[u * 6 + v];        // broadcast LDS
#pragma unroll
                    for (int ox = 0; ox < 25; ox++)
                        acc[ox] = fmaf(zv, xrow[ox + v], acc[ox]);
                }
            }
            float* op = ob + (size_t)oc * 625 + lane * 25;
#pragma unroll
            for (int ox = 0; ox < 25; ox++) op[ox] = acc[ox];
        }
    }
}

// ============================ launch =========================================
extern "C" void kernel_launch(void* const* d_in, const int* in_sizes, int n_in,
                              void* d_out, int out_size) {
    const float* z = (const float*)d_in[0];
    const float* x = (const float*)d_in[1];

    PrepArgs pa;
    for (int p = 0; p < 4; p++) {
        pa.w[p] = (const float*)d_in[2 + p * 5 + 0];
        pa.g[p] = (const float*)d_in[2 + p * 5 + 1];
        pa.b[p] = (const float*)d_in[2 + p * 5 + 2];
        pa.m[p] = (const float*)d_in[2 + p * 5 + 3];
        pa.v[p] = (const float*)d_in[2 + p * 5 + 4];
    }

    cudaFuncSetAttribute(wino_gemm,
                         cudaFuncAttributeMaxDynamicSharedMemorySize, GEMM_SMEM);
    cudaFuncSetAttribute(wino_gemm,
                         cudaFuncAttributePreferredSharedMemoryCarveout, 100);
    cudaFuncSetAttribute(prep_xform,
                         cudaFuncAttributeMaxDynamicSharedMemorySize, XF_SMEM);
    cudaFuncSetAttribute(inv_xcorr,
                         cudaFuncAttributeMaxDynamicSharedMemorySize, IX_SMEM);

    prep_xform<<<2944, 256, XF_SMEM>>>(x, pa);
    xform_z<<<dim3(32, 32), 128>>>(z);
    wino_gemm<<<3840, 128, GEMM_SMEM>>>();
    inv_xcorr<<<dim3(16, 32, 2), 256, IX_SMEM>>>((float*)d_out);
}